// round 1
// baseline (speedup 1.0000x reference)
#include <cuda_runtime.h>

// ---------------- problem dims ----------------
#define B_    32
#define NS    128
#define SD    256
#define NF    4096
#define MH    1024
#define NMT   32          // number of 128-wide feature tiles (4096/128)

// ---------------- device scratch ----------------
__device__ float g_h[4][64];
__device__ float g_Wq [SD*SD];          // [256,256]
__device__ float g_Wg [SD*2*SD];        // [256,512]
__device__ float g_Wf0[MH*2*SD];        // [1024,512]
__device__ float g_Wf1[SD*MH];          // [256,1024]
__device__ float g_snA[B_*NS*SD];
__device__ float g_snF[B_*NS*SD];
__device__ float g_q  [B_*NS*SD];
__device__ float g_srow[B_*NMT*NS];
__device__ float g_part[(size_t)B_*NMT*NS*SD];   // 134 MB partials
__device__ float g_fattn[B_*NS*SD];
__device__ float g_Hbuf[B_*NS*MH];

// ---------------- 1) time-dependent weight MLP heads ----------------
__global__ void tdw_kernel(const float* t,
    const float* qw0,const float* qb0,const float* qw1,const float* qb1,
    const float* gw0,const float* gb0,const float* gw1,const float* gb1,
    const float* f0w0,const float* f0b0,const float* f0w1,const float* f0b1,
    const float* f1w0,const float* f1b0,const float* f1w1,const float* f1b1)
{
    __shared__ float emb[257];
    __shared__ float h0[64];
    const float* w0s[4] = {qw0,gw0,f0w0,f1w0};
    const float* b0s[4] = {qb0,gb0,f0b0,f1b0};
    const float* w1s[4] = {qw1,gw1,f0w1,f1w1};
    const float* b1s[4] = {qb1,gb1,f0b1,f1b1};
    int head = blockIdx.x;
    int tid  = threadIdx.x;
    float tv = t[0];
    const float C = -9.210340371976184f / 128.0f;   // -ln(10000)/128
    for (int j = tid; j < 257; j += blockDim.x) {
        float e;
        if (j == 0)        e = tv;
        else if (j <= 128) e = sinf(C * (float)(j-1)   * tv);
        else               e = cosf(C * (float)(j-129) * tv);
        emb[j] = e;
    }
    __syncthreads();
    int warp = tid >> 5, lane = tid & 31;
    const float* w0 = w0s[head];
    for (int r = warp; r < 64; r += 4) {
        float s = 0.f;
        for (int j = lane; j < 257; j += 32) s += w0[r*257 + j] * emb[j];
        #pragma unroll
        for (int o = 16; o; o >>= 1) s += __shfl_xor_sync(0xffffffffu, s, o);
        if (lane == 0) {
            s += b0s[head][r];
            h0[r] = s / (1.f + expf(-s));
        }
    }
    __syncthreads();
    if (tid < 64) {
        const float* w1 = w1s[head];
        float s = 0.f;
        #pragma unroll 8
        for (int j = 0; j < 64; j++) s += w1[tid*64 + j] * h0[j];
        s += b1s[head][tid];
        g_h[head][tid] = s / (1.f + expf(-s));
    }
}

// ---------------- 2) materialize W = wp @ h + bp ----------------
__global__ void wmat_kernel(const float* __restrict__ wp,
                            const float* __restrict__ bp,
                            int which, int rows)
{
    float* W = (which==0) ? g_Wq : (which==1) ? g_Wg : (which==2) ? g_Wf0 : g_Wf1;
    int lane = threadIdx.x & 31;
    int half = lane >> 4;
    int sub  = lane & 15;
    float4 hv = *(const float4*)&g_h[which][sub*4];
    int gwarp = (blockIdx.x * blockDim.x + threadIdx.x) >> 5;
    int r = gwarp * 2 + half;
    if (r >= rows) return;
    const float4 w4 = *(const float4*)&wp[(size_t)r*64 + sub*4];
    float p = w4.x*hv.x + w4.y*hv.y + w4.z*hv.z + w4.w*hv.w;
    p += __shfl_down_sync(0xffffffffu, p, 8);
    p += __shfl_down_sync(0xffffffffu, p, 4);
    p += __shfl_down_sync(0xffffffffu, p, 2);
    p += __shfl_down_sync(0xffffffffu, p, 1);
    if (sub == 0) W[r] = p + bp[r];
}

// ---------------- 3) dual LayerNorm ----------------
__global__ void ln_kernel(const float* __restrict__ slots,
                          const float* __restrict__ aw, const float* __restrict__ ab,
                          const float* __restrict__ fw, const float* __restrict__ fb)
{
    int warp = threadIdx.x >> 5, lane = threadIdx.x & 31;
    int row  = blockIdx.x * 8 + warp;          // 4096 rows total
    const float* x = slots + (size_t)row * 256;
    float4 x0 = *(const float4*)&x[lane*4];
    float4 x1 = *(const float4*)&x[128 + lane*4];
    float s = x0.x+x0.y+x0.z+x0.w + x1.x+x1.y+x1.z+x1.w;
    #pragma unroll
    for (int o = 16; o; o >>= 1) s += __shfl_xor_sync(0xffffffffu, s, o);
    float mu = s * (1.f/256.f);
    float d, q = 0.f;
    d = x0.x-mu; q += d*d;  d = x0.y-mu; q += d*d;
    d = x0.z-mu; q += d*d;  d = x0.w-mu; q += d*d;
    d = x1.x-mu; q += d*d;  d = x1.y-mu; q += d*d;
    d = x1.z-mu; q += d*d;  d = x1.w-mu; q += d*d;
    #pragma unroll
    for (int o = 16; o; o >>= 1) q += __shfl_xor_sync(0xffffffffu, q, o);
    float rstd = rsqrtf(q * (1.f/256.f) + 1e-5f);

    float4 aw0 = *(const float4*)&aw[lane*4],      aw1 = *(const float4*)&aw[128+lane*4];
    float4 ab0 = *(const float4*)&ab[lane*4],      ab1 = *(const float4*)&ab[128+lane*4];
    float4 fw0 = *(const float4*)&fw[lane*4],      fw1 = *(const float4*)&fw[128+lane*4];
    float4 fb0 = *(const float4*)&fb[lane*4],      fb1 = *(const float4*)&fb[128+lane*4];

    float4 yA0, yA1, yF0, yF1;
    yA0.x = (x0.x-mu)*rstd*aw0.x + ab0.x;  yA0.y = (x0.y-mu)*rstd*aw0.y + ab0.y;
    yA0.z = (x0.z-mu)*rstd*aw0.z + ab0.z;  yA0.w = (x0.w-mu)*rstd*aw0.w + ab0.w;
    yA1.x = (x1.x-mu)*rstd*aw1.x + ab1.x;  yA1.y = (x1.y-mu)*rstd*aw1.y + ab1.y;
    yA1.z = (x1.z-mu)*rstd*aw1.z + ab1.z;  yA1.w = (x1.w-mu)*rstd*aw1.w + ab1.w;
    yF0.x = (x0.x-mu)*rstd*fw0.x + fb0.x;  yF0.y = (x0.y-mu)*rstd*fw0.y + fb0.y;
    yF0.z = (x0.z-mu)*rstd*fw0.z + fb0.z;  yF0.w = (x0.w-mu)*rstd*fw0.w + fb0.w;
    yF1.x = (x1.x-mu)*rstd*fw1.x + fb1.x;  yF1.y = (x1.y-mu)*rstd*fw1.y + fb1.y;
    yF1.z = (x1.z-mu)*rstd*fw1.z + fb1.z;  yF1.w = (x1.w-mu)*rstd*fw1.w + fb1.w;

    *(float4*)&g_snA[(size_t)row*256 + lane*4]       = yA0;
    *(float4*)&g_snA[(size_t)row*256 + 128 + lane*4] = yA1;
    *(float4*)&g_snF[(size_t)row*256 + lane*4]       = yF0;
    *(float4*)&g_snF[(size_t)row*256 + 128 + lane*4] = yF1;
}

// ---------------- 4) q = snA @ Wq^T   (M=4096,N=256,K=256) ----------------
__global__ __launch_bounds__(256) void gemm_q_kernel()
{
    __shared__ float As[16][68];
    __shared__ float Bs[16][68];
    int tid = threadIdx.x, tx = tid & 15, ty = tid >> 4;
    int bm = blockIdx.x * 64, bn = blockIdx.y * 64;
    int lr = tid >> 2, lc = tid & 3;
    float c[4][4] = {};
    for (int k0 = 0; k0 < 256; k0 += 16) {
        float4 a4 = *(const float4*)&g_snA[(size_t)(bm+lr)*256 + k0 + lc*4];
        float4 b4 = *(const float4*)&g_Wq [(size_t)(bn+lr)*256 + k0 + lc*4];
        __syncthreads();
        As[lc*4+0][lr]=a4.x; As[lc*4+1][lr]=a4.y; As[lc*4+2][lr]=a4.z; As[lc*4+3][lr]=a4.w;
        Bs[lc*4+0][lr]=b4.x; Bs[lc*4+1][lr]=b4.y; Bs[lc*4+2][lr]=b4.z; Bs[lc*4+3][lr]=b4.w;
        __syncthreads();
        #pragma unroll
        for (int kk = 0; kk < 16; kk++) {
            float a_r[4], b_r[4];
            *(float4*)a_r = *(const float4*)&As[kk][ty*4];
            *(float4*)b_r = *(const float4*)&Bs[kk][tx*4];
            #pragma unroll
            for (int i = 0; i < 4; i++)
                #pragma unroll
                for (int j = 0; j < 4; j++) c[i][j] += a_r[i]*b_r[j];
        }
    }
    #pragma unroll
    for (int i = 0; i < 4; i++) {
        float4 o; o.x=c[i][0]; o.y=c[i][1]; o.z=c[i][2]; o.w=c[i][3];
        *(float4*)&g_q[(size_t)(bm+ty*4+i)*256 + bn + tx*4] = o;
    }
}

// ---------------- 5) attention: logits + col-softmax + rowsum + att@V ----------------
__global__ __launch_bounds__(256) void attn_kernel(const float* __restrict__ Kin,
                                                   const float* __restrict__ Vin)
{
    extern __shared__ float sm[];
    float* l_s = sm;               // [128][132]
    float* As  = sm;               // alias [16][132]
    float* Bs  = sm + 16*132;      // alias [16][132]
    float* v_s = sm + 128*132;     // [16][128]
    int b = blockIdx.x, mt = blockIdx.y;
    int tid = threadIdx.x, tx = tid & 15, ty = tid >> 4;
    const float* Q  = g_q + (size_t)b*128*256;
    const float* Kb = Kin + ((size_t)b*NF + mt*128)*256;
    const float* Vb = Vin + ((size_t)b*NF + mt*128)*256;

    // --- stage 1: L = Q @ K^T * scale  (128x128, k=256) ---
    float c[8][8];
    #pragma unroll
    for (int i=0;i<8;i++)
        #pragma unroll
        for (int j=0;j<8;j++) c[i][j]=0.f;

    int f0 = tid*2,   r0 = f0>>2, c0 = f0&3;
    int f1 = tid*2+1, r1 = f1>>2, c1 = f1&3;
    for (int k0 = 0; k0 < 256; k0 += 16) {
        float4 a0 = *(const float4*)&Q [r0*256 + k0 + c0*4];
        float4 a1 = *(const float4*)&Q [r1*256 + k0 + c1*4];
        float4 b0 = *(const float4*)&Kb[r0*256 + k0 + c0*4];
        float4 b1 = *(const float4*)&Kb[r1*256 + k0 + c1*4];
        __syncthreads();
        As[(c0*4+0)*132+r0]=a0.x; As[(c0*4+1)*132+r0]=a0.y; As[(c0*4+2)*132+r0]=a0.z; As[(c0*4+3)*132+r0]=a0.w;
        As[(c1*4+0)*132+r1]=a1.x; As[(c1*4+1)*132+r1]=a1.y; As[(c1*4+2)*132+r1]=a1.z; As[(c1*4+3)*132+r1]=a1.w;
        Bs[(c0*4+0)*132+r0]=b0.x; Bs[(c0*4+1)*132+r0]=b0.y; Bs[(c0*4+2)*132+r0]=b0.z; Bs[(c0*4+3)*132+r0]=b0.w;
        Bs[(c1*4+0)*132+r1]=b1.x; Bs[(c1*4+1)*132+r1]=b1.y; Bs[(c1*4+2)*132+r1]=b1.z; Bs[(c1*4+3)*132+r1]=b1.w;
        __syncthreads();
        #pragma unroll
        for (int kk = 0; kk < 16; kk++) {
            float a_r[8], b_r[8];
            *(float4*)&a_r[0] = *(const float4*)&As[kk*132 + ty*8];
            *(float4*)&a_r[4] = *(const float4*)&As[kk*132 + ty*8 + 4];
            *(float4*)&b_r[0] = *(const float4*)&Bs[kk*132 + tx*8];
            *(float4*)&b_r[4] = *(const float4*)&Bs[kk*132 + tx*8 + 4];
            #pragma unroll
            for (int i=0;i<8;i++)
                #pragma unroll
                for (int j=0;j<8;j++) c[i][j] += a_r[i]*b_r[j];
        }
    }
    __syncthreads();
    const float scale = 0.0625f;   // 256^-0.5
    #pragma unroll
    for (int i = 0; i < 8; i++) {
        float4 o0, o1;
        o0.x=c[i][0]*scale; o0.y=c[i][1]*scale; o0.z=c[i][2]*scale; o0.w=c[i][3]*scale;
        o1.x=c[i][4]*scale; o1.y=c[i][5]*scale; o1.z=c[i][6]*scale; o1.w=c[i][7]*scale;
        *(float4*)&l_s[(ty*8+i)*132 + tx*8]     = o0;
        *(float4*)&l_s[(ty*8+i)*132 + tx*8 + 4] = o1;
    }
    __syncthreads();

    // --- stage 2: exact softmax over n (column), per column m ---
    if (tid < 128) {
        int m = tid;
        float mx = -1e30f;
        for (int n = 0; n < 128; n++) mx = fmaxf(mx, l_s[n*132 + m]);
        float s = 0.f;
        for (int n = 0; n < 128; n++) {
            float e = expf(l_s[n*132 + m] - mx);
            l_s[n*132 + m] = e;
            s += e;
        }
        float inv = 1.f / s;
        for (int n = 0; n < 128; n++) l_s[n*132 + m] *= inv;
    }
    __syncthreads();
    if (tid < 128) {                       // row sums for feature-renorm
        int n = tid; float s = 0.f;
        for (int m = 0; m < 128; m++) s += l_s[n*132 + m];
        g_srow[(b*NMT + mt)*128 + n] = s;
    }

    // --- stage 3: P = att @ V_tile (128x256), write per-tile partial ---
    float* P = g_part + (size_t)((b*NMT + mt)*128)*256;
    int fv0 = tid*2,   vr0 = fv0>>5, vc0 = fv0&31;
    int fv1 = tid*2+1, vr1 = fv1>>5, vc1 = fv1&31;
    for (int dh = 0; dh < 2; dh++) {
        float acc[8][8];
        #pragma unroll
        for (int i=0;i<8;i++)
            #pragma unroll
            for (int j=0;j<8;j++) acc[i][j]=0.f;
        for (int m0 = 0; m0 < 128; m0 += 16) {
            float4 v0 = *(const float4*)&Vb[(m0+vr0)*256 + dh*128 + vc0*4];
            float4 v1 = *(const float4*)&Vb[(m0+vr1)*256 + dh*128 + vc1*4];
            __syncthreads();
            *(float4*)&v_s[vr0*128 + vc0*4] = v0;
            *(float4*)&v_s[vr1*128 + vc1*4] = v1;
            __syncthreads();
            #pragma unroll
            for (int kk = 0; kk < 16; kk++) {
                float a_r[8], b_r[8];
                #pragma unroll
                for (int i=0;i<8;i++) a_r[i] = l_s[(ty*8+i)*132 + m0 + kk];
                *(float4*)&b_r[0] = *(const float4*)&v_s[kk*128 + tx*8];
                *(float4*)&b_r[4] = *(const float4*)&v_s[kk*128 + tx*8 + 4];
                #pragma unroll
                for (int i=0;i<8;i++)
                    #pragma unroll
                    for (int j=0;j<8;j++) acc[i][j] += a_r[i]*b_r[j];
            }
        }
        #pragma unroll
        for (int i = 0; i < 8; i++) {
            float4 o0, o1;
            o0.x=acc[i][0]; o0.y=acc[i][1]; o0.z=acc[i][2]; o0.w=acc[i][3];
            o1.x=acc[i][4]; o1.y=acc[i][5]; o1.z=acc[i][6]; o1.w=acc[i][7];
            *(float4*)&P[(ty*8+i)*256 + dh*128 + tx*8]     = o0;
            *(float4*)&P[(ty*8+i)*256 + dh*128 + tx*8 + 4] = o1;
        }
    }
}

// ---------------- 6) reduce partials + renorm by (s+1e-8) ----------------
__global__ void reduce_kernel()
{
    __shared__ float ssh[32];
    int b = blockIdx.x >> 7, n = blockIdx.x & 127;
    int tid = threadIdx.x;
    if (tid < 32) ssh[tid] = g_srow[(b*NMT + tid)*128 + n];
    __syncthreads();
    float s = 0.f;
    #pragma unroll
    for (int i = 0; i < 32; i++) s += ssh[i];
    float inv = 1.f / (s + 1e-8f);
    const float* p = g_part + ((size_t)(b*NMT)*128 + n)*256 + tid;
    float acc = 0.f;
    #pragma unroll 8
    for (int mt = 0; mt < 32; mt++) acc += p[(size_t)mt*128*256];
    g_fattn[((size_t)b*128 + n)*256 + tid] = acc * inv;
}

// ---------------- 7) H = relu([snF|fattn] @ Wf0^T)  (M=4096,N=1024,K=512) ----------------
__global__ __launch_bounds__(256) void gemm_ff0_kernel()
{
    __shared__ float As[16][68];
    __shared__ float Bs[16][68];
    int tid = threadIdx.x, tx = tid & 15, ty = tid >> 4;
    int bm = blockIdx.x * 64, bn = blockIdx.y * 64;
    int lr = tid >> 2, lc = tid & 3;
    float c[4][4] = {};
    for (int k0 = 0; k0 < 512; k0 += 16) {
        int kg = k0 + lc*4;
        const float* asrc = (kg < 256) ? &g_snF [(size_t)(bm+lr)*256 + kg]
                                       : &g_fattn[(size_t)(bm+lr)*256 + kg - 256];
        float4 a4 = *(const float4*)asrc;
        float4 b4 = *(const float4*)&g_Wf0[(size_t)(bn+lr)*512 + kg];
        __syncthreads();
        As[lc*4+0][lr]=a4.x; As[lc*4+1][lr]=a4.y; As[lc*4+2][lr]=a4.z; As[lc*4+3][lr]=a4.w;
        Bs[lc*4+0][lr]=b4.x; Bs[lc*4+1][lr]=b4.y; Bs[lc*4+2][lr]=b4.z; Bs[lc*4+3][lr]=b4.w;
        __syncthreads();
        #pragma unroll
        for (int kk = 0; kk < 16; kk++) {
            float a_r[4], b_r[4];
            *(float4*)a_r = *(const float4*)&As[kk][ty*4];
            *(float4*)b_r = *(const float4*)&Bs[kk][tx*4];
            #pragma unroll
            for (int i = 0; i < 4; i++)
                #pragma unroll
                for (int j = 0; j < 4; j++) c[i][j] += a_r[i]*b_r[j];
        }
    }
    #pragma unroll
    for (int i = 0; i < 4; i++) {
        float4 o;
        o.x=fmaxf(c[i][0],0.f); o.y=fmaxf(c[i][1],0.f);
        o.z=fmaxf(c[i][2],0.f); o.w=fmaxf(c[i][3],0.f);
        *(float4*)&g_Hbuf[(size_t)(bm+ty*4+i)*1024 + bn + tx*4] = o;
    }
}

// ---------------- 8) out = sigmoid([snA|fattn]@Wg^T)*fattn + H@Wf1^T ----------------
__global__ __launch_bounds__(256) void gemm_out_kernel(float* __restrict__ out)
{
    __shared__ float As[16][68];
    __shared__ float Bs[16][68];
    int tid = threadIdx.x, tx = tid & 15, ty = tid >> 4;
    int bm = blockIdx.x * 64, bn = blockIdx.y * 64;
    int lr = tid >> 2, lc = tid & 3;
    float cg[4][4] = {}, cf[4][4] = {};
    // pass 1: gate logits, K = 512
    for (int k0 = 0; k0 < 512; k0 += 16) {
        int kg = k0 + lc*4;
        const float* asrc = (kg < 256) ? &g_snA [(size_t)(bm+lr)*256 + kg]
                                       : &g_fattn[(size_t)(bm+lr)*256 + kg - 256];
        float4 a4 = *(const float4*)asrc;
        float4 b4 = *(const float4*)&g_Wg[(size_t)(bn+lr)*512 + kg];
        __syncthreads();
        As[lc*4+0][lr]=a4.x; As[lc*4+1][lr]=a4.y; As[lc*4+2][lr]=a4.z; As[lc*4+3][lr]=a4.w;
        Bs[lc*4+0][lr]=b4.x; Bs[lc*4+1][lr]=b4.y; Bs[lc*4+2][lr]=b4.z; Bs[lc*4+3][lr]=b4.w;
        __syncthreads();
        #pragma unroll
        for (int kk = 0; kk < 16; kk++) {
            float a_r[4], b_r[4];
            *(float4*)a_r = *(const float4*)&As[kk][ty*4];
            *(float4*)b_r = *(const float4*)&Bs[kk][tx*4];
            #pragma unroll
            for (int i = 0; i < 4; i++)
                #pragma unroll
                for (int j = 0; j < 4; j++) cg[i][j] += a_r[i]*b_r[j];
        }
    }
    // pass 2: ff1, K = 1024
    for (int k0 = 0; k0 < 1024; k0 += 16) {
        int kg = k0 + lc*4;
        float4 a4 = *(const float4*)&g_Hbuf[(size_t)(bm+lr)*1024 + kg];
        float4 b4 = *(const float4*)&g_Wf1 [(size_t)(bn+lr)*1024 + kg];
        __syncthreads();
        As[lc*4+0][lr]=a4.x; As[lc*4+1][lr]=a4.y; As[lc*4+2][lr]=a4.z; As[lc*4+3][lr]=a4.w;
        Bs[lc*4+0][lr]=b4.x; Bs[lc*4+1][lr]=b4.y; Bs[lc*4+2][lr]=b4.z; Bs[lc*4+3][lr]=b4.w;
        __syncthreads();
        #pragma unroll
        for (int kk = 0; kk < 16; kk++) {
            float a_r[4], b_r[4];
            *(float4*)a_r = *(const float4*)&As[kk][ty*4];
            *(float4*)b_r = *(const float4*)&Bs[kk][tx*4];
            #pragma unroll
            for (int i = 0; i < 4; i++)
                #pragma unroll
                for (int j = 0; j < 4; j++) cf[i][j] += a_r[i]*b_r[j];
        }
    }
    #pragma unroll
    for (int i = 0; i < 4; i++) {
        int r = bm + ty*4 + i;
        float4 fa = *(const float4*)&g_fattn[(size_t)r*256 + bn + tx*4];
        float4 o;
        o.x = fa.x / (1.f + expf(-cg[i][0])) + cf[i][0];
        o.y = fa.y / (1.f + expf(-cg[i][1])) + cf[i][1];
        o.z = fa.z / (1.f + expf(-cg[i][2])) + cf[i][2];
        o.w = fa.w / (1.f + expf(-cg[i][3])) + cf[i][3];
        *(float4*)&out[(size_t)r*256 + bn + tx*4] = o;
    }
}

// ---------------- host launcher ----------------
extern "C" void kernel_launch(void* const* d_in, const int* in_sizes, int n_in,
                              void* d_out, int out_size)
{
    const float *t, *slots, *kin, *vin;
    const float *w0[4], *b0[4], *w1[4], *b1[4], *wp[4], *bp[4];
    const float *lnAw, *lnAb, *lnFw, *lnFb;

    if (in_sizes[0] == 1) {
        // reference-signature order: t, slots, k, v, heads..., ln...
        t     = (const float*)d_in[0];
        slots = (const float*)d_in[1];
        kin   = (const float*)d_in[2];
        vin   = (const float*)d_in[3];
        for (int h = 0; h < 4; h++) {
            int base = 4 + h*6;
            w0[h] = (const float*)d_in[base+0];  b0[h] = (const float*)d_in[base+1];
            w1[h] = (const float*)d_in[base+2];  b1[h] = (const float*)d_in[base+3];
            wp[h] = (const float*)d_in[base+4];  bp[h] = (const float*)d_in[base+5];
        }
        lnAw = (const float*)d_in[28]; lnAb = (const float*)d_in[29];
        lnFw = (const float*)d_in[30]; lnFb = (const float*)d_in[31];
    } else {
        // setup_inputs dict order: heads..., ln..., t, slots, k, v
        for (int h = 0; h < 4; h++) {
            int base = h*6;
            w0[h] = (const float*)d_in[base+0];  b0[h] = (const float*)d_in[base+1];
            w1[h] = (const float*)d_in[base+2];  b1[h] = (const float*)d_in[base+3];
            wp[h] = (const float*)d_in[base+4];  bp[h] = (const float*)d_in[base+5];
        }
        lnAw = (const float*)d_in[24]; lnAb = (const float*)d_in[25];
        lnFw = (const float*)d_in[26]; lnFb = (const float*)d_in[27];
        t     = (const float*)d_in[28];
        slots = (const float*)d_in[29];
        kin   = (const float*)d_in[30];
        vin   = (const float*)d_in[31];
    }

    // 1) time MLP heads
    tdw_kernel<<<4, 128>>>(t,
        w0[0],b0[0],w1[0],b1[0],  w0[1],b0[1],w1[1],b1[1],
        w0[2],b0[2],w1[2],b1[2],  w0[3],b0[3],w1[3],b1[3]);

    // 2) materialize W matrices
    wmat_kernel<<< (SD*SD)/16,     256>>>(wp[0], bp[0], 0, SD*SD);
    wmat_kernel<<< (SD*2*SD)/16,   256>>>(wp[1], bp[1], 1, SD*2*SD);
    wmat_kernel<<< (MH*2*SD)/16,   256>>>(wp[2], bp[2], 2, MH*2*SD);
    wmat_kernel<<< (SD*MH)/16,     256>>>(wp[3], bp[3], 3, SD*MH);

    // 3) layernorms
    ln_kernel<<<(B_*NS)/8, 256>>>(slots, lnAw, lnAb, lnFw, lnFb);

    // 4) q projection
    gemm_q_kernel<<<dim3(64, 4), 256>>>();

    // 5) attention
    static const int attn_smem = (128*132 + 16*128) * 4;   // 75776 B
    cudaFuncSetAttribute(attn_kernel, cudaFuncAttributeMaxDynamicSharedMemorySize, attn_smem);
    attn_kernel<<<dim3(B_, NMT), 256, attn_smem>>>(kin, vin);

    // 6) reduce partials + renorm
    reduce_kernel<<<B_*NS, 256>>>();

    // 7) FF hidden
    gemm_ff0_kernel<<<dim3(64, 16), 256>>>();

    // 8) gate + ff1 + output
    gemm_out_kernel<<<dim3(64, 4), 256>>>((float*)d_out);
}

// round 2
// speedup vs baseline: 2.5902x; 2.5902x over previous
#include <cuda_runtime.h>

// ---------------- problem dims ----------------
#define B_    32
#define NS    128
#define SD    256
#define NF    4096
#define MH    1024
#define NMT   32

// ---------------- device scratch ----------------
__device__ float g_h[4][64];
__device__ float g_Wq [SD*SD];
__device__ float g_Wg [SD*2*SD];
__device__ float g_Wf0[MH*2*SD];
__device__ float g_Wf1[SD*MH];
__device__ float g_snA[B_*NS*SD];
__device__ float g_snF[B_*NS*SD];
__device__ float g_q  [B_*NS*SD];
__device__ float g_att[(size_t)B_*NS*NF];       // 64 MB normalized probs
__device__ float g_srow[B_*NMT*NS];
__device__ float g_rowinv[B_*NS];
__device__ float g_avp[(size_t)2*B_*NS*SD];     // split-K partials
__device__ float g_fattn[B_*NS*SD];
__device__ float g_Hbuf[B_*NS*MH];

// ---------------- tf32 helpers ----------------
__device__ __forceinline__ unsigned f2tf(float f) {
    unsigned u;
    asm("cvt.rna.tf32.f32 %0, %1;" : "=r"(u) : "f"(f));
    return u;
}
__device__ __forceinline__ void mma8(float c[4], const unsigned a[4], const unsigned b[2]) {
    asm("mma.sync.aligned.m16n8k8.row.col.f32.tf32.tf32.f32 "
        "{%0,%1,%2,%3},{%4,%5,%6,%7},{%8,%9},{%0,%1,%2,%3};\n"
        : "+f"(c[0]), "+f"(c[1]), "+f"(c[2]), "+f"(c[3])
        : "r"(a[0]), "r"(a[1]), "r"(a[2]), "r"(a[3]), "r"(b[0]), "r"(b[1]));
}

#define SWZ(d) ((d) + (((d) >> 4) << 2))

// select source row pointer for (possibly concatenated) A
__device__ __forceinline__ const float* rowptr(const float* s0, int ld0,
                                               const float* s1, int ld1,
                                               int split, int r, int k) {
    return (k < split) ? (s0 + (size_t)r * ld0 + k)
                       : (s1 + (size_t)r * ld1 + (k - split));
}

// ---- staging: load 128x32 row-major tile into float4 regs ----
__device__ __forceinline__ void ldg_rm(float4 p[4], const float* s0, int ld0,
                                       const float* s1, int ld1, int split,
                                       int k0, int tid) {
    int r = tid >> 1, c0 = (tid & 1) * 16;
    const float* p0 = rowptr(s0, ld0, s1, ld1, split, r, k0 + c0);
    #pragma unroll
    for (int j = 0; j < 4; j++) p[j] = *(const float4*)(p0 + 4*j);
}
__device__ __forceinline__ void sts_rm(unsigned* S, const float4 p[4], int tid) {
    int r = tid >> 1, c0 = (tid & 1) * 16;
    #pragma unroll
    for (int j = 0; j < 4; j++) {
        uint4 u;
        u.x = f2tf(p[j].x); u.y = f2tf(p[j].y);
        u.z = f2tf(p[j].z); u.w = f2tf(p[j].w);
        *(uint4*)&S[r*36 + c0 + 4*j] = u;
    }
}
// ---- staging for k-major B (V tile: 32 k-rows x 128 n-cols) ----
__device__ __forceinline__ void ldg_kn(float4 p[4], const float* src, int ld,
                                       int k0, int tid) {
    int m = tid >> 3, dg = (tid & 7) * 16;
    const float* p0 = src + (size_t)(k0 + m) * ld + dg;
    #pragma unroll
    for (int j = 0; j < 4; j++) p[j] = *(const float4*)(p0 + 4*j);
}
__device__ __forceinline__ void sts_kn(unsigned* S, const float4 p[4], int tid) {
    int m = tid >> 3, dg = (tid & 7) * 16;
    #pragma unroll
    for (int j = 0; j < 4; j++) {
        int d = dg + 4*j;
        uint4 u;
        u.x = f2tf(p[j].x); u.y = f2tf(p[j].y);
        u.z = f2tf(p[j].z); u.w = f2tf(p[j].w);
        *(uint4*)&S[m*168 + SWZ(d)] = u;
    }
}

// ---- inner compute: one BK=32 chunk, B in [n][k] layout ----
__device__ __forceinline__ void comp_nk(const unsigned* As, const unsigned* Bs,
                                        float acc[2][8][4], int wr, int wc,
                                        int g, int t) {
    #pragma unroll
    for (int ks = 0; ks < 4; ks++) {
        int kk = ks * 8 + t;
        unsigned a[2][4];
        #pragma unroll
        for (int mt = 0; mt < 2; mt++) {
            int r = wr + mt*16 + g;
            a[mt][0] = As[r*36 + kk];
            a[mt][1] = As[(r+8)*36 + kk];
            a[mt][2] = As[r*36 + kk + 4];
            a[mt][3] = As[(r+8)*36 + kk + 4];
        }
        #pragma unroll
        for (int nt = 0; nt < 8; nt++) {
            int n = wc + nt*8 + g;
            unsigned b[2];
            b[0] = Bs[n*36 + kk];
            b[1] = Bs[n*36 + kk + 4];
            #pragma unroll
            for (int mt = 0; mt < 2; mt++) mma8(acc[mt][nt], a[mt], b);
        }
    }
}
// ---- inner compute: B in [k][n] swizzled layout (AV) ----
__device__ __forceinline__ void comp_kn(const unsigned* As, const unsigned* Bs,
                                        float acc[2][8][4], int wr, int wc,
                                        int g, int t) {
    #pragma unroll
    for (int ks = 0; ks < 4; ks++) {
        int kk = ks * 8 + t;
        unsigned a[2][4];
        #pragma unroll
        for (int mt = 0; mt < 2; mt++) {
            int r = wr + mt*16 + g;
            a[mt][0] = As[r*36 + kk];
            a[mt][1] = As[(r+8)*36 + kk];
            a[mt][2] = As[r*36 + kk + 4];
            a[mt][3] = As[(r+8)*36 + kk + 4];
        }
        #pragma unroll
        for (int nt = 0; nt < 8; nt++) {
            int n = wc + nt*8 + g;
            unsigned b[2];
            b[0] = Bs[kk*168 + SWZ(n)];
            b[1] = Bs[(kk+4)*168 + SWZ(n)];
            #pragma unroll
            for (int mt = 0; mt < 2; mt++) mma8(acc[mt][nt], a[mt], b);
        }
    }
}

// full pipelined K loop, B row-major [n][k]
__device__ __forceinline__ void gemm_nk(unsigned* As, unsigned* Bs,
                                        const float* a0, int lda0,
                                        const float* a1, int lda1, int split,
                                        const float* b, int ldb,
                                        int nchunks, float acc[2][8][4],
                                        int wr, int wc, int g, int t, int tid) {
    float4 pa[4], pb[4];
    ldg_rm(pa, a0, lda0, a1, lda1, split, 0, tid);
    ldg_rm(pb, b, ldb, b, ldb, 1 << 30, 0, tid);
    for (int c = 0; c < nchunks; c++) {
        __syncthreads();
        sts_rm(As, pa, tid);
        sts_rm(Bs, pb, tid);
        __syncthreads();
        if (c + 1 < nchunks) {
            ldg_rm(pa, a0, lda0, a1, lda1, split, (c+1)*32, tid);
            ldg_rm(pb, b, ldb, b, ldb, 1 << 30, (c+1)*32, tid);
        }
        comp_nk(As, Bs, acc, wr, wc, g, t);
    }
}

// ---------------- 1) time-dependent weight MLP heads ----------------
__global__ void tdw_kernel(const float* t,
    const float* qw0,const float* qb0,const float* qw1,const float* qb1,
    const float* gw0,const float* gb0,const float* gw1,const float* gb1,
    const float* f0w0,const float* f0b0,const float* f0w1,const float* f0b1,
    const float* f1w0,const float* f1b0,const float* f1w1,const float* f1b1)
{
    __shared__ float emb[257];
    __shared__ float h0[64];
    const float* w0s[4] = {qw0,gw0,f0w0,f1w0};
    const float* b0s[4] = {qb0,gb0,f0b0,f1b0};
    const float* w1s[4] = {qw1,gw1,f0w1,f1w1};
    const float* b1s[4] = {qb1,gb1,f0b1,f1b1};
    int head = blockIdx.x;
    int tid  = threadIdx.x;
    float tv = t[0];
    const float C = -9.210340371976184f / 128.0f;
    for (int j = tid; j < 257; j += blockDim.x) {
        float e;
        if (j == 0)        e = tv;
        else if (j <= 128) e = sinf(C * (float)(j-1)   * tv);
        else               e = cosf(C * (float)(j-129) * tv);
        emb[j] = e;
    }
    __syncthreads();
    int warp = tid >> 5, lane = tid & 31;
    const float* w0 = w0s[head];
    for (int r = warp; r < 64; r += 4) {
        float s = 0.f;
        for (int j = lane; j < 257; j += 32) s += w0[r*257 + j] * emb[j];
        #pragma unroll
        for (int o = 16; o; o >>= 1) s += __shfl_xor_sync(0xffffffffu, s, o);
        if (lane == 0) { s += b0s[head][r]; h0[r] = s / (1.f + expf(-s)); }
    }
    __syncthreads();
    if (tid < 64) {
        const float* w1 = w1s[head];
        float s = 0.f;
        #pragma unroll 8
        for (int j = 0; j < 64; j++) s += w1[tid*64 + j] * h0[j];
        s += b1s[head][tid];
        g_h[head][tid] = s / (1.f + expf(-s));
    }
}

// ---------------- 2) materialize W = wp @ h + bp ----------------
__global__ void wmat_kernel(const float* __restrict__ wp,
                            const float* __restrict__ bp,
                            int which, int rows)
{
    float* W = (which==0) ? g_Wq : (which==1) ? g_Wg : (which==2) ? g_Wf0 : g_Wf1;
    int lane = threadIdx.x & 31;
    int half = lane >> 4;
    int sub  = lane & 15;
    float4 hv = *(const float4*)&g_h[which][sub*4];
    int gwarp = (blockIdx.x * blockDim.x + threadIdx.x) >> 5;
    int r = gwarp * 2 + half;
    if (r >= rows) return;
    const float4 w4 = *(const float4*)&wp[(size_t)r*64 + sub*4];
    float p = w4.x*hv.x + w4.y*hv.y + w4.z*hv.z + w4.w*hv.w;
    p += __shfl_down_sync(0xffffffffu, p, 8);
    p += __shfl_down_sync(0xffffffffu, p, 4);
    p += __shfl_down_sync(0xffffffffu, p, 2);
    p += __shfl_down_sync(0xffffffffu, p, 1);
    if (sub == 0) W[r] = p + bp[r];
}

// ---------------- 3) dual LayerNorm ----------------
__global__ void ln_kernel(const float* __restrict__ slots,
                          const float* __restrict__ aw, const float* __restrict__ ab,
                          const float* __restrict__ fw, const float* __restrict__ fb)
{
    int warp = threadIdx.x >> 5, lane = threadIdx.x & 31;
    int row  = blockIdx.x * 8 + warp;
    const float* x = slots + (size_t)row * 256;
    float4 x0 = *(const float4*)&x[lane*4];
    float4 x1 = *(const float4*)&x[128 + lane*4];
    float s = x0.x+x0.y+x0.z+x0.w + x1.x+x1.y+x1.z+x1.w;
    #pragma unroll
    for (int o = 16; o; o >>= 1) s += __shfl_xor_sync(0xffffffffu, s, o);
    float mu = s * (1.f/256.f);
    float d, q = 0.f;
    d = x0.x-mu; q += d*d;  d = x0.y-mu; q += d*d;
    d = x0.z-mu; q += d*d;  d = x0.w-mu; q += d*d;
    d = x1.x-mu; q += d*d;  d = x1.y-mu; q += d*d;
    d = x1.z-mu; q += d*d;  d = x1.w-mu; q += d*d;
    #pragma unroll
    for (int o = 16; o; o >>= 1) q += __shfl_xor_sync(0xffffffffu, q, o);
    float rstd = rsqrtf(q * (1.f/256.f) + 1e-5f);

    float4 aw0 = *(const float4*)&aw[lane*4],  aw1 = *(const float4*)&aw[128+lane*4];
    float4 ab0 = *(const float4*)&ab[lane*4],  ab1 = *(const float4*)&ab[128+lane*4];
    float4 fw0 = *(const float4*)&fw[lane*4],  fw1 = *(const float4*)&fw[128+lane*4];
    float4 fb0 = *(const float4*)&fb[lane*4],  fb1 = *(const float4*)&fb[128+lane*4];

    float4 yA0, yA1, yF0, yF1;
    yA0.x = (x0.x-mu)*rstd*aw0.x + ab0.x;  yA0.y = (x0.y-mu)*rstd*aw0.y + ab0.y;
    yA0.z = (x0.z-mu)*rstd*aw0.z + ab0.z;  yA0.w = (x0.w-mu)*rstd*aw0.w + ab0.w;
    yA1.x = (x1.x-mu)*rstd*aw1.x + ab1.x;  yA1.y = (x1.y-mu)*rstd*aw1.y + ab1.y;
    yA1.z = (x1.z-mu)*rstd*aw1.z + ab1.z;  yA1.w = (x1.w-mu)*rstd*aw1.w + ab1.w;
    yF0.x = (x0.x-mu)*rstd*fw0.x + fb0.x;  yF0.y = (x0.y-mu)*rstd*fw0.y + fb0.y;
    yF0.z = (x0.z-mu)*rstd*fw0.z + fb0.z;  yF0.w = (x0.w-mu)*rstd*fw0.w + fb0.w;
    yF1.x = (x1.x-mu)*rstd*fw1.x + fb1.x;  yF1.y = (x1.y-mu)*rstd*fw1.y + fb1.y;
    yF1.z = (x1.z-mu)*rstd*fw1.z + fb1.z;  yF1.w = (x1.w-mu)*rstd*fw1.w + fb1.w;

    *(float4*)&g_snA[(size_t)row*256 + lane*4]       = yA0;
    *(float4*)&g_snA[(size_t)row*256 + 128 + lane*4] = yA1;
    *(float4*)&g_snF[(size_t)row*256 + lane*4]       = yF0;
    *(float4*)&g_snF[(size_t)row*256 + 128 + lane*4] = yF1;
}

// ---------------- 4) q = snA @ Wq^T (tf32) ----------------
__global__ __launch_bounds__(256) void gemm_q_tf32()
{
    __shared__ unsigned As[128*36];
    __shared__ unsigned Bs[128*36];
    int tid = threadIdx.x, lane = tid & 31;
    int g = lane >> 2, t = lane & 3;
    int wid = tid >> 5, wr = (wid >> 1) * 32, wc = (wid & 1) * 64;
    int bm = blockIdx.x * 128, bn = blockIdx.y * 128;
    float acc[2][8][4] = {};
    gemm_nk(As, Bs, g_snA + (size_t)bm*256, 256, g_snA, 256, 1<<30,
            g_Wq + (size_t)bn*256, 256, 8, acc, wr, wc, g, t, tid);
    #pragma unroll
    for (int mt = 0; mt < 2; mt++)
        #pragma unroll
        for (int nt = 0; nt < 8; nt++) {
            int r = bm + wr + mt*16 + g, c = bn + wc + nt*8 + 2*t;
            *(float2*)&g_q[(size_t)r*256 + c]     = make_float2(acc[mt][nt][0], acc[mt][nt][1]);
            *(float2*)&g_q[(size_t)(r+8)*256 + c] = make_float2(acc[mt][nt][2], acc[mt][nt][3]);
        }
}

// ---------------- 5) QK^T + softmax(tile-local) → att probs ----------------
__global__ __launch_bounds__(256) void attn_qk_kernel(const float* __restrict__ Kin)
{
    extern __shared__ unsigned sm_u[];
    unsigned* As = sm_u;
    unsigned* Bs = sm_u + 128*36;
    float*    L  = (float*)(sm_u + 2*128*36);      // [128][133]
    int b = blockIdx.x, mt_ = blockIdx.y;
    int tid = threadIdx.x, lane = tid & 31;
    int g = lane >> 2, t = lane & 3;
    int wid = tid >> 5, wr = (wid >> 1) * 32, wc = (wid & 1) * 64;
    const float* Q  = g_q + (size_t)b*128*256;
    const float* Kb = Kin + ((size_t)b*NF + mt_*128)*256;
    float acc[2][8][4] = {};
    gemm_nk(As, Bs, Q, 256, Q, 256, 1<<30, Kb, 256, 8, acc, wr, wc, g, t, tid);
    const float scale = 0.0625f;
    #pragma unroll
    for (int mt = 0; mt < 2; mt++)
        #pragma unroll
        for (int nt = 0; nt < 8; nt++) {
            int r = wr + mt*16 + g, c = wc + nt*8 + 2*t;
            L[r*133 + c]       = acc[mt][nt][0]*scale;
            L[r*133 + c + 1]   = acc[mt][nt][1]*scale;
            L[(r+8)*133 + c]   = acc[mt][nt][2]*scale;
            L[(r+8)*133 + c+1] = acc[mt][nt][3]*scale;
        }
    __syncthreads();
    if (tid < 128) {                   // exact softmax over slots (rows), per column
        int m = tid;
        float mx = -1e30f;
        #pragma unroll 4
        for (int n = 0; n < 128; n++) mx = fmaxf(mx, L[n*133 + m]);
        float s = 0.f;
        #pragma unroll 4
        for (int n = 0; n < 128; n++) {
            float e = __expf(L[n*133 + m] - mx);
            L[n*133 + m] = e;  s += e;
        }
        float inv = 1.f / s;
        #pragma unroll 4
        for (int n = 0; n < 128; n++) L[n*133 + m] *= inv;
    }
    __syncthreads();
    if (tid < 128) {                   // per-slot partial sums over features
        int n = tid; float rs = 0.f;
        #pragma unroll 4
        for (int m = 0; m < 128; m++) rs += L[n*133 + m];
        g_srow[(b*NMT + mt_)*128 + n] = rs;
    }
    // write normalized probs
    int n = tid >> 1, mh = (tid & 1) * 64;
    float* dst = g_att + ((size_t)b*128 + n)*NF + mt_*128 + mh;
    #pragma unroll
    for (int j = 0; j < 16; j++) {
        float4 v;
        v.x = L[n*133 + mh + 4*j];     v.y = L[n*133 + mh + 4*j + 1];
        v.z = L[n*133 + mh + 4*j + 2]; v.w = L[n*133 + mh + 4*j + 3];
        *(float4*)(dst + 4*j) = v;
    }
}

// ---------------- 6) row-sum reduce → 1/(s+eps) ----------------
__global__ void rowinv_kernel()
{
    int b = blockIdx.x, n = threadIdx.x;
    float s = 0.f;
    #pragma unroll 8
    for (int mt = 0; mt < NMT; mt++) s += g_srow[(b*NMT + mt)*128 + n];
    g_rowinv[b*128 + n] = 1.f / (s + 1e-8f);
}

// ---------------- 7) att @ V (split-K=2, tf32) ----------------
__global__ __launch_bounds__(256) void attn_av_kernel(const float* __restrict__ Vin)
{
    __shared__ unsigned As[128*36];
    __shared__ unsigned Bs[32*168];
    int b = blockIdx.x, dt = blockIdx.y, ks_ = blockIdx.z;
    int tid = threadIdx.x, lane = tid & 31;
    int g = lane >> 2, t = lane & 3;
    int wid = tid >> 5, wr = (wid >> 1) * 32, wc = (wid & 1) * 64;
    const float* A = g_att + (size_t)b*128*NF + ks_*2048;
    const float* Bv = Vin + ((size_t)b*NF + ks_*2048)*256 + dt*128;
    float acc[2][8][4] = {};
    float4 pa[4], pb[4];
    ldg_rm(pa, A, NF, A, NF, 1<<30, 0, tid);
    ldg_kn(pb, Bv, 256, 0, tid);
    for (int c = 0; c < 64; c++) {
        __syncthreads();
        sts_rm(As, pa, tid);
        sts_kn(Bs, pb, tid);
        __syncthreads();
        if (c + 1 < 64) {
            ldg_rm(pa, A, NF, A, NF, 1<<30, (c+1)*32, tid);
            ldg_kn(pb, Bv, 256, (c+1)*32, tid);
        }
        comp_kn(As, Bs, acc, wr, wc, g, t);
    }
    float* P = g_avp + (((size_t)ks_*B_ + b)*128)*256 + dt*128;
    #pragma unroll
    for (int mt = 0; mt < 2; mt++)
        #pragma unroll
        for (int nt = 0; nt < 8; nt++) {
            int r = wr + mt*16 + g, c = wc + nt*8 + 2*t;
            *(float2*)&P[(size_t)r*256 + c]     = make_float2(acc[mt][nt][0], acc[mt][nt][1]);
            *(float2*)&P[(size_t)(r+8)*256 + c] = make_float2(acc[mt][nt][2], acc[mt][nt][3]);
        }
}

// ---------------- 8) combine split-K + renorm ----------------
__global__ void av_combine_kernel()
{
    int idx = blockIdx.x * 256 + threadIdx.x;      // float4 index
    int row = idx >> 6;
    float inv = g_rowinv[row];
    float4 p0 = *(float4*)&g_avp[(size_t)idx*4];
    float4 p1 = *(float4*)&g_avp[(size_t)B_*NS*SD + (size_t)idx*4];
    float4 o;
    o.x = (p0.x + p1.x) * inv;  o.y = (p0.y + p1.y) * inv;
    o.z = (p0.z + p1.z) * inv;  o.w = (p0.w + p1.w) * inv;
    *(float4*)&g_fattn[(size_t)idx*4] = o;
}

// ---------------- 9) H = relu([snF|fattn] @ Wf0^T) (tf32) ----------------
__global__ __launch_bounds__(256) void gemm_ff0_tf32()
{
    __shared__ unsigned As[128*36];
    __shared__ unsigned Bs[128*36];
    int tid = threadIdx.x, lane = tid & 31;
    int g = lane >> 2, t = lane & 3;
    int wid = tid >> 5, wr = (wid >> 1) * 32, wc = (wid & 1) * 64;
    int bm = blockIdx.x * 128, bn = blockIdx.y * 128;
    float acc[2][8][4] = {};
    gemm_nk(As, Bs, g_snF + (size_t)bm*256, 256, g_fattn + (size_t)bm*256, 256, 256,
            g_Wf0 + (size_t)bn*512, 512, 16, acc, wr, wc, g, t, tid);
    #pragma unroll
    for (int mt = 0; mt < 2; mt++)
        #pragma unroll
        for (int nt = 0; nt < 8; nt++) {
            int r = bm + wr + mt*16 + g, c = bn + wc + nt*8 + 2*t;
            *(float2*)&g_Hbuf[(size_t)r*1024 + c] =
                make_float2(fmaxf(acc[mt][nt][0],0.f), fmaxf(acc[mt][nt][1],0.f));
            *(float2*)&g_Hbuf[(size_t)(r+8)*1024 + c] =
                make_float2(fmaxf(acc[mt][nt][2],0.f), fmaxf(acc[mt][nt][3],0.f));
        }
}

// ---------------- 10) out = sigmoid([snA|fattn]@Wg^T)*fattn + H@Wf1^T ----------------
__global__ __launch_bounds__(256) void gemm_out_tf32(float* __restrict__ out)
{
    __shared__ unsigned As[128*36];
    __shared__ unsigned Bs[128*36];
    int tid = threadIdx.x, lane = tid & 31;
    int g = lane >> 2, t = lane & 3;
    int wid = tid >> 5, wr = (wid >> 1) * 32, wc = (wid & 1) * 64;
    int bm = blockIdx.x * 128, bn = blockIdx.y * 128;
    float acc[2][8][4] = {};
    // pass 1: gate logits
    gemm_nk(As, Bs, g_snA + (size_t)bm*256, 256, g_fattn + (size_t)bm*256, 256, 256,
            g_Wg + (size_t)bn*512, 512, 16, acc, wr, wc, g, t, tid);
    // transform in place: acc := fattn * sigmoid(acc)
    #pragma unroll
    for (int mt = 0; mt < 2; mt++)
        #pragma unroll
        for (int nt = 0; nt < 8; nt++) {
            int r = bm + wr + mt*16 + g, c = bn + wc + nt*8 + 2*t;
            float2 f0 = *(const float2*)&g_fattn[(size_t)r*256 + c];
            float2 f1 = *(const float2*)&g_fattn[(size_t)(r+8)*256 + c];
            acc[mt][nt][0] = f0.x / (1.f + __expf(-acc[mt][nt][0]));
            acc[mt][nt][1] = f0.y / (1.f + __expf(-acc[mt][nt][1]));
            acc[mt][nt][2] = f1.x / (1.f + __expf(-acc[mt][nt][2]));
            acc[mt][nt][3] = f1.y / (1.f + __expf(-acc[mt][nt][3]));
        }
    // pass 2: accumulate H @ Wf1^T on top
    gemm_nk(As, Bs, g_Hbuf + (size_t)bm*1024, 1024, g_Hbuf, 1024, 1<<30,
            g_Wf1 + (size_t)bn*1024, 1024, 32, acc, wr, wc, g, t, tid);
    #pragma unroll
    for (int mt = 0; mt < 2; mt++)
        #pragma unroll
        for (int nt = 0; nt < 8; nt++) {
            int r = bm + wr + mt*16 + g, c = bn + wc + nt*8 + 2*t;
            *(float2*)&out[(size_t)r*256 + c]     = make_float2(acc[mt][nt][0], acc[mt][nt][1]);
            *(float2*)&out[(size_t)(r+8)*256 + c] = make_float2(acc[mt][nt][2], acc[mt][nt][3]);
        }
}

// ---------------- host launcher ----------------
extern "C" void kernel_launch(void* const* d_in, const int* in_sizes, int n_in,
                              void* d_out, int out_size)
{
    const float *t, *slots, *kin, *vin;
    const float *w0[4], *b0[4], *w1[4], *b1[4], *wp[4], *bp[4];
    const float *lnAw, *lnAb, *lnFw, *lnFb;

    if (in_sizes[0] == 1) {
        t     = (const float*)d_in[0];
        slots = (const float*)d_in[1];
        kin   = (const float*)d_in[2];
        vin   = (const float*)d_in[3];
        for (int h = 0; h < 4; h++) {
            int base = 4 + h*6;
            w0[h] = (const float*)d_in[base+0];  b0[h] = (const float*)d_in[base+1];
            w1[h] = (const float*)d_in[base+2];  b1[h] = (const float*)d_in[base+3];
            wp[h] = (const float*)d_in[base+4];  bp[h] = (const float*)d_in[base+5];
        }
        lnAw = (const float*)d_in[28]; lnAb = (const float*)d_in[29];
        lnFw = (const float*)d_in[30]; lnFb = (const float*)d_in[31];
    } else {
        for (int h = 0; h < 4; h++) {
            int base = h*6;
            w0[h] = (const float*)d_in[base+0];  b0[h] = (const float*)d_in[base+1];
            w1[h] = (const float*)d_in[base+2];  b1[h] = (const float*)d_in[base+3];
            wp[h] = (const float*)d_in[base+4];  bp[h] = (const float*)d_in[base+5];
        }
        lnAw = (const float*)d_in[24]; lnAb = (const float*)d_in[25];
        lnFw = (const float*)d_in[26]; lnFb = (const float*)d_in[27];
        t     = (const float*)d_in[28];
        slots = (const float*)d_in[29];
        kin   = (const float*)d_in[30];
        vin   = (const float*)d_in[31];
    }

    tdw_kernel<<<4, 128>>>(t,
        w0[0],b0[0],w1[0],b1[0],  w0[1],b0[1],w1[1],b1[1],
        w0[2],b0[2],w1[2],b1[2],  w0[3],b0[3],w1[3],b1[3]);

    wmat_kernel<<< (SD*SD)/16,   256>>>(wp[0], bp[0], 0, SD*SD);
    wmat_kernel<<< (SD*2*SD)/16, 256>>>(wp[1], bp[1], 1, SD*2*SD);
    wmat_kernel<<< (MH*2*SD)/16, 256>>>(wp[2], bp[2], 2, MH*2*SD);
    wmat_kernel<<< (SD*MH)/16,   256>>>(wp[3], bp[3], 3, SD*MH);

    ln_kernel<<<(B_*NS)/8, 256>>>(slots, lnAw, lnAb, lnFw, lnFb);

    gemm_q_tf32<<<dim3(32, 2), 256>>>();

    static int attn_smem = (2*128*36 + 128*133) * 4;   // 104960 B
    cudaFuncSetAttribute(attn_qk_kernel, cudaFuncAttributeMaxDynamicSharedMemorySize, attn_smem);
    attn_qk_kernel<<<dim3(B_, NMT), 256, attn_smem>>>(kin);

    rowinv_kernel<<<B_, 128>>>();

    attn_av_kernel<<<dim3(B_, 2, 2), 256>>>(vin);

    av_combine_kernel<<<(B_*NS*SD/4)/256, 256>>>();

    gemm_ff0_tf32<<<dim3(32, 8), 256>>>();

    gemm_out_tf32<<<dim3(32, 2), 256>>>((float*)d_out);
}

// round 3
// speedup vs baseline: 2.6117x; 1.0083x over previous
#include <cuda_runtime.h>

// ---------------- problem dims ----------------
#define B_    32
#define NS    128
#define SD    256
#define NF    4096
#define MH    1024
#define NMT   32

// ---------------- device scratch ----------------
__device__ float g_h[4][64];
__device__ float g_Wq [SD*SD];
__device__ float g_Wg [SD*2*SD];
__device__ float g_Wf0[MH*2*SD];
__device__ float g_Wf1[SD*MH];
__device__ float g_snA[B_*NS*SD];
__device__ float g_snF[B_*NS*SD];
__device__ float g_q  [B_*NS*SD];
__device__ float g_att[(size_t)B_*NS*NF];       // 64 MB normalized probs
__device__ float g_srow[B_*NMT*NS];
__device__ float g_rowinv[B_*NS];
__device__ float g_avp[(size_t)2*B_*NS*SD];     // split-K partials
__device__ float g_fattn[B_*NS*SD];
__device__ float g_Hbuf[B_*NS*MH];

// ---------------- tf32 helpers ----------------
__device__ __forceinline__ unsigned f2tf(float f) {
    unsigned u;
    asm("cvt.rna.tf32.f32 %0, %1;" : "=r"(u) : "f"(f));
    return u;
}
__device__ __forceinline__ void mma8(float c[4], const unsigned a[4], const unsigned b[2]) {
    asm("mma.sync.aligned.m16n8k8.row.col.f32.tf32.tf32.f32 "
        "{%0,%1,%2,%3},{%4,%5,%6,%7},{%8,%9},{%0,%1,%2,%3};\n"
        : "+f"(c[0]), "+f"(c[1]), "+f"(c[2]), "+f"(c[3])
        : "r"(a[0]), "r"(a[1]), "r"(a[2]), "r"(a[3]), "r"(b[0]), "r"(b[1]));
}

#define SWZ(d) ((d) + (((d) >> 4) << 2))

// select source row pointer for (possibly concatenated) A
__device__ __forceinline__ const float* rowptr(const float* s0, int ld0,
                                               const float* s1, int ld1,
                                               int split, int r, int k) {
    return (k < split) ? (s0 + (size_t)r * ld0 + k)
                       : (s1 + (size_t)r * ld1 + (k - split));
}

// ---- staging: load 128x32 row-major tile into float4 regs ----
__device__ __forceinline__ void ldg_rm(float4 p[4], const float* s0, int ld0,
                                       const float* s1, int ld1, int split,
                                       int k0, int tid) {
    int r = tid >> 1, c0 = (tid & 1) * 16;
    const float* p0 = rowptr(s0, ld0, s1, ld1, split, r, k0 + c0);
    #pragma unroll
    for (int j = 0; j < 4; j++) p[j] = *(const float4*)(p0 + 4*j);
}
__device__ __forceinline__ void sts_rm(unsigned* S, const float4 p[4], int tid) {
    int r = tid >> 1, c0 = (tid & 1) * 16;
    #pragma unroll
    for (int j = 0; j < 4; j++) {
        uint4 u;
        u.x = f2tf(p[j].x); u.y = f2tf(p[j].y);
        u.z = f2tf(p[j].z); u.w = f2tf(p[j].w);
        *(uint4*)&S[r*36 + c0 + 4*j] = u;
    }
}
// ---- staging for k-major B (V tile: 32 k-rows x 128 n-cols) ----
__device__ __forceinline__ void ldg_kn(float4 p[4], const float* src, int ld,
                                       int k0, int tid) {
    int m = tid >> 3, dg = (tid & 7) * 16;
    const float* p0 = src + (size_t)(k0 + m) * ld + dg;
    #pragma unroll
    for (int j = 0; j < 4; j++) p[j] = *(const float4*)(p0 + 4*j);
}
__device__ __forceinline__ void sts_kn(unsigned* S, const float4 p[4], int tid) {
    int m = tid >> 3, dg = (tid & 7) * 16;
    #pragma unroll
    for (int j = 0; j < 4; j++) {
        int d = dg + 4*j;
        uint4 u;
        u.x = f2tf(p[j].x); u.y = f2tf(p[j].y);
        u.z = f2tf(p[j].z); u.w = f2tf(p[j].w);
        *(uint4*)&S[m*168 + SWZ(d)] = u;
    }
}

// ---- inner compute: one BK=32 chunk, B in [n][k] layout ----
__device__ __forceinline__ void comp_nk(const unsigned* As, const unsigned* Bs,
                                        float acc[2][8][4], int wr, int wc,
                                        int g, int t) {
    #pragma unroll
    for (int ks = 0; ks < 4; ks++) {
        int kk = ks * 8 + t;
        unsigned a[2][4];
        #pragma unroll
        for (int mt = 0; mt < 2; mt++) {
            int r = wr + mt*16 + g;
            a[mt][0] = As[r*36 + kk];
            a[mt][1] = As[(r+8)*36 + kk];
            a[mt][2] = As[r*36 + kk + 4];
            a[mt][3] = As[(r+8)*36 + kk + 4];
        }
        #pragma unroll
        for (int nt = 0; nt < 8; nt++) {
            int n = wc + nt*8 + g;
            unsigned b[2];
            b[0] = Bs[n*36 + kk];
            b[1] = Bs[n*36 + kk + 4];
            #pragma unroll
            for (int mt = 0; mt < 2; mt++) mma8(acc[mt][nt], a[mt], b);
        }
    }
}
// ---- inner compute: B in [k][n] swizzled layout (AV) ----
__device__ __forceinline__ void comp_kn(const unsigned* As, const unsigned* Bs,
                                        float acc[2][8][4], int wr, int wc,
                                        int g, int t) {
    #pragma unroll
    for (int ks = 0; ks < 4; ks++) {
        int kk = ks * 8 + t;
        unsigned a[2][4];
        #pragma unroll
        for (int mt = 0; mt < 2; mt++) {
            int r = wr + mt*16 + g;
            a[mt][0] = As[r*36 + kk];
            a[mt][1] = As[(r+8)*36 + kk];
            a[mt][2] = As[r*36 + kk + 4];
            a[mt][3] = As[(r+8)*36 + kk + 4];
        }
        #pragma unroll
        for (int nt = 0; nt < 8; nt++) {
            int n = wc + nt*8 + g;
            unsigned b[2];
            b[0] = Bs[kk*168 + SWZ(n)];
            b[1] = Bs[(kk+4)*168 + SWZ(n)];
            #pragma unroll
            for (int mt = 0; mt < 2; mt++) mma8(acc[mt][nt], a[mt], b);
        }
    }
}

// full pipelined K loop, B row-major [n][k]
__device__ __forceinline__ void gemm_nk(unsigned* As, unsigned* Bs,
                                        const float* a0, int lda0,
                                        const float* a1, int lda1, int split,
                                        const float* b, int ldb,
                                        int nchunks, float acc[2][8][4],
                                        int wr, int wc, int g, int t, int tid) {
    float4 pa[4], pb[4];
    ldg_rm(pa, a0, lda0, a1, lda1, split, 0, tid);
    ldg_rm(pb, b, ldb, b, ldb, 1 << 30, 0, tid);
    for (int c = 0; c < nchunks; c++) {
        __syncthreads();
        sts_rm(As, pa, tid);
        sts_rm(Bs, pb, tid);
        __syncthreads();
        if (c + 1 < nchunks) {
            ldg_rm(pa, a0, lda0, a1, lda1, split, (c+1)*32, tid);
            ldg_rm(pb, b, ldb, b, ldb, 1 << 30, (c+1)*32, tid);
        }
        comp_nk(As, Bs, acc, wr, wc, g, t);
    }
}

// ---------------- 1) time-dependent weight MLP heads ----------------
__global__ void tdw_kernel(const float* t,
    const float* qw0,const float* qb0,const float* qw1,const float* qb1,
    const float* gw0,const float* gb0,const float* gw1,const float* gb1,
    const float* f0w0,const float* f0b0,const float* f0w1,const float* f0b1,
    const float* f1w0,const float* f1b0,const float* f1w1,const float* f1b1)
{
    __shared__ float emb[257];
    __shared__ float h0[64];
    const float* w0s[4] = {qw0,gw0,f0w0,f1w0};
    const float* b0s[4] = {qb0,gb0,f0b0,f1b0};
    const float* w1s[4] = {qw1,gw1,f0w1,f1w1};
    const float* b1s[4] = {qb1,gb1,f0b1,f1b1};
    int head = blockIdx.x;
    int tid  = threadIdx.x;
    float tv = t[0];
    const float C = -9.210340371976184f / 128.0f;
    for (int j = tid; j < 257; j += blockDim.x) {
        float e;
        if (j == 0)        e = tv;
        else if (j <= 128) e = sinf(C * (float)(j-1)   * tv);
        else               e = cosf(C * (float)(j-129) * tv);
        emb[j] = e;
    }
    __syncthreads();
    int warp = tid >> 5, lane = tid & 31;
    const float* w0 = w0s[head];
    for (int r = warp; r < 64; r += 4) {
        float s = 0.f;
        for (int j = lane; j < 257; j += 32) s += w0[r*257 + j] * emb[j];
        #pragma unroll
        for (int o = 16; o; o >>= 1) s += __shfl_xor_sync(0xffffffffu, s, o);
        if (lane == 0) { s += b0s[head][r]; h0[r] = s / (1.f + expf(-s)); }
    }
    __syncthreads();
    if (tid < 64) {
        const float* w1 = w1s[head];
        float s = 0.f;
        #pragma unroll 8
        for (int j = 0; j < 64; j++) s += w1[tid*64 + j] * h0[j];
        s += b1s[head][tid];
        g_h[head][tid] = s / (1.f + expf(-s));
    }
}

// ---------------- 2) materialize W = wp @ h + bp ----------------
__global__ void wmat_kernel(const float* __restrict__ wp,
                            const float* __restrict__ bp,
                            int which, int rows)
{
    float* W = (which==0) ? g_Wq : (which==1) ? g_Wg : (which==2) ? g_Wf0 : g_Wf1;
    int lane = threadIdx.x & 31;
    int half = lane >> 4;
    int sub  = lane & 15;
    float4 hv = *(const float4*)&g_h[which][sub*4];
    int gwarp = (blockIdx.x * blockDim.x + threadIdx.x) >> 5;
    int r = gwarp * 2 + half;
    if (r >= rows) return;
    const float4 w4 = *(const float4*)&wp[(size_t)r*64 + sub*4];
    float p = w4.x*hv.x + w4.y*hv.y + w4.z*hv.z + w4.w*hv.w;
    p += __shfl_down_sync(0xffffffffu, p, 8);
    p += __shfl_down_sync(0xffffffffu, p, 4);
    p += __shfl_down_sync(0xffffffffu, p, 2);
    p += __shfl_down_sync(0xffffffffu, p, 1);
    if (sub == 0) W[r] = p + bp[r];
}

// ---------------- 3) dual LayerNorm ----------------
__global__ void ln_kernel(const float* __restrict__ slots,
                          const float* __restrict__ aw, const float* __restrict__ ab,
                          const float* __restrict__ fw, const float* __restrict__ fb)
{
    int warp = threadIdx.x >> 5, lane = threadIdx.x & 31;
    int row  = blockIdx.x * 8 + warp;
    const float* x = slots + (size_t)row * 256;
    float4 x0 = *(const float4*)&x[lane*4];
    float4 x1 = *(const float4*)&x[128 + lane*4];
    float s = x0.x+x0.y+x0.z+x0.w + x1.x+x1.y+x1.z+x1.w;
    #pragma unroll
    for (int o = 16; o; o >>= 1) s += __shfl_xor_sync(0xffffffffu, s, o);
    float mu = s * (1.f/256.f);
    float d, q = 0.f;
    d = x0.x-mu; q += d*d;  d = x0.y-mu; q += d*d;
    d = x0.z-mu; q += d*d;  d = x0.w-mu; q += d*d;
    d = x1.x-mu; q += d*d;  d = x1.y-mu; q += d*d;
    d = x1.z-mu; q += d*d;  d = x1.w-mu; q += d*d;
    #pragma unroll
    for (int o = 16; o; o >>= 1) q += __shfl_xor_sync(0xffffffffu, q, o);
    float rstd = rsqrtf(q * (1.f/256.f) + 1e-5f);

    float4 aw0 = *(const float4*)&aw[lane*4],  aw1 = *(const float4*)&aw[128+lane*4];
    float4 ab0 = *(const float4*)&ab[lane*4],  ab1 = *(const float4*)&ab[128+lane*4];
    float4 fw0 = *(const float4*)&fw[lane*4],  fw1 = *(const float4*)&fw[128+lane*4];
    float4 fb0 = *(const float4*)&fb[lane*4],  fb1 = *(const float4*)&fb[128+lane*4];

    float4 yA0, yA1, yF0, yF1;
    yA0.x = (x0.x-mu)*rstd*aw0.x + ab0.x;  yA0.y = (x0.y-mu)*rstd*aw0.y + ab0.y;
    yA0.z = (x0.z-mu)*rstd*aw0.z + ab0.z;  yA0.w = (x0.w-mu)*rstd*aw0.w + ab0.w;
    yA1.x = (x1.x-mu)*rstd*aw1.x + ab1.x;  yA1.y = (x1.y-mu)*rstd*aw1.y + ab1.y;
    yA1.z = (x1.z-mu)*rstd*aw1.z + ab1.z;  yA1.w = (x1.w-mu)*rstd*aw1.w + ab1.w;
    yF0.x = (x0.x-mu)*rstd*fw0.x + fb0.x;  yF0.y = (x0.y-mu)*rstd*fw0.y + fb0.y;
    yF0.z = (x0.z-mu)*rstd*fw0.z + fb0.z;  yF0.w = (x0.w-mu)*rstd*fw0.w + fb0.w;
    yF1.x = (x1.x-mu)*rstd*fw1.x + fb1.x;  yF1.y = (x1.y-mu)*rstd*fw1.y + fb1.y;
    yF1.z = (x1.z-mu)*rstd*fw1.z + fb1.z;  yF1.w = (x1.w-mu)*rstd*fw1.w + fb1.w;

    *(float4*)&g_snA[(size_t)row*256 + lane*4]       = yA0;
    *(float4*)&g_snA[(size_t)row*256 + 128 + lane*4] = yA1;
    *(float4*)&g_snF[(size_t)row*256 + lane*4]       = yF0;
    *(float4*)&g_snF[(size_t)row*256 + 128 + lane*4] = yF1;
}

// ---------------- 4) q = snA @ Wq^T (tf32) ----------------
__global__ __launch_bounds__(256) void gemm_q_tf32()
{
    __shared__ unsigned As[128*36];
    __shared__ unsigned Bs[128*36];
    int tid = threadIdx.x, lane = tid & 31;
    int g = lane >> 2, t = lane & 3;
    int wid = tid >> 5, wr = (wid >> 1) * 32, wc = (wid & 1) * 64;
    int bm = blockIdx.x * 128, bn = blockIdx.y * 128;
    float acc[2][8][4] = {};
    gemm_nk(As, Bs, g_snA + (size_t)bm*256, 256, g_snA, 256, 1<<30,
            g_Wq + (size_t)bn*256, 256, 8, acc, wr, wc, g, t, tid);
    #pragma unroll
    for (int mt = 0; mt < 2; mt++)
        #pragma unroll
        for (int nt = 0; nt < 8; nt++) {
            int r = bm + wr + mt*16 + g, c = bn + wc + nt*8 + 2*t;
            *(float2*)&g_q[(size_t)r*256 + c]     = make_float2(acc[mt][nt][0], acc[mt][nt][1]);
            *(float2*)&g_q[(size_t)(r+8)*256 + c] = make_float2(acc[mt][nt][2], acc[mt][nt][3]);
        }
}

// ---------------- 5) QK^T + softmax(tile-local) → att probs ----------------
__global__ __launch_bounds__(256) void attn_qk_kernel(const float* __restrict__ Kin)
{
    extern __shared__ unsigned sm_u[];
    unsigned* As = sm_u;
    unsigned* Bs = sm_u + 128*36;
    float*    L  = (float*)(sm_u + 2*128*36);      // [128][133]
    int b = blockIdx.x, mt_ = blockIdx.y;
    int tid = threadIdx.x, lane = tid & 31;
    int g = lane >> 2, t = lane & 3;
    int wid = tid >> 5, wr = (wid >> 1) * 32, wc = (wid & 1) * 64;
    const float* Q  = g_q + (size_t)b*128*256;
    const float* Kb = Kin + ((size_t)b*NF + mt_*128)*256;
    float acc[2][8][4] = {};
    gemm_nk(As, Bs, Q, 256, Q, 256, 1<<30, Kb, 256, 8, acc, wr, wc, g, t, tid);
    const float scale = 0.0625f;
    #pragma unroll
    for (int mt = 0; mt < 2; mt++)
        #pragma unroll
        for (int nt = 0; nt < 8; nt++) {
            int r = wr + mt*16 + g, c = wc + nt*8 + 2*t;
            L[r*133 + c]       = acc[mt][nt][0]*scale;
            L[r*133 + c + 1]   = acc[mt][nt][1]*scale;
            L[(r+8)*133 + c]   = acc[mt][nt][2]*scale;
            L[(r+8)*133 + c+1] = acc[mt][nt][3]*scale;
        }
    __syncthreads();
    if (tid < 128) {                   // exact softmax over slots (rows), per column
        int m = tid;
        float mx = -1e30f;
        #pragma unroll 4
        for (int n = 0; n < 128; n++) mx = fmaxf(mx, L[n*133 + m]);
        float s = 0.f;
        #pragma unroll 4
        for (int n = 0; n < 128; n++) {
            float e = __expf(L[n*133 + m] - mx);
            L[n*133 + m] = e;  s += e;
        }
        float inv = 1.f / s;
        #pragma unroll 4
        for (int n = 0; n < 128; n++) L[n*133 + m] *= inv;
    }
    __syncthreads();
    if (tid < 128) {                   // per-slot partial sums over features
        int n = tid; float rs = 0.f;
        #pragma unroll 4
        for (int m = 0; m < 128; m++) rs += L[n*133 + m];
        g_srow[(b*NMT + mt_)*128 + n] = rs;
    }
    // write normalized probs
    int n = tid >> 1, mh = (tid & 1) * 64;
    float* dst = g_att + ((size_t)b*128 + n)*NF + mt_*128 + mh;
    #pragma unroll
    for (int j = 0; j < 16; j++) {
        float4 v;
        v.x = L[n*133 + mh + 4*j];     v.y = L[n*133 + mh + 4*j + 1];
        v.z = L[n*133 + mh + 4*j + 2]; v.w = L[n*133 + mh + 4*j + 3];
        *(float4*)(dst + 4*j) = v;
    }
}

// ---------------- 6) row-sum reduce → 1/(s+eps) ----------------
__global__ void rowinv_kernel()
{
    int b = blockIdx.x, n = threadIdx.x;
    float s = 0.f;
    #pragma unroll 8
    for (int mt = 0; mt < NMT; mt++) s += g_srow[(b*NMT + mt)*128 + n];
    g_rowinv[b*128 + n] = 1.f / (s + 1e-8f);
}

// ---------------- 7) att @ V (split-K=2, tf32) ----------------
__global__ __launch_bounds__(256) void attn_av_kernel(const float* __restrict__ Vin)
{
    __shared__ unsigned As[128*36];
    __shared__ unsigned Bs[32*168];
    int b = blockIdx.x, dt = blockIdx.y, ks_ = blockIdx.z;
    int tid = threadIdx.x, lane = tid & 31;
    int g = lane >> 2, t = lane & 3;
    int wid = tid >> 5, wr = (wid >> 1) * 32, wc = (wid & 1) * 64;
    const float* A = g_att + (size_t)b*128*NF + ks_*2048;
    const float* Bv = Vin + ((size_t)b*NF + ks_*2048)*256 + dt*128;
    float acc[2][8][4] = {};
    float4 pa[4], pb[4];
    ldg_rm(pa, A, NF, A, NF, 1<<30, 0, tid);
    ldg_kn(pb, Bv, 256, 0, tid);
    for (int c = 0; c < 64; c++) {
        __syncthreads();
        sts_rm(As, pa, tid);
        sts_kn(Bs, pb, tid);
        __syncthreads();
        if (c + 1 < 64) {
            ldg_rm(pa, A, NF, A, NF, 1<<30, (c+1)*32, tid);
            ldg_kn(pb, Bv, 256, (c+1)*32, tid);
        }
        comp_kn(As, Bs, acc, wr, wc, g, t);
    }
    float* P = g_avp + (((size_t)ks_*B_ + b)*128)*256 + dt*128;
    #pragma unroll
    for (int mt = 0; mt < 2; mt++)
        #pragma unroll
        for (int nt = 0; nt < 8; nt++) {
            int r = wr + mt*16 + g, c = wc + nt*8 + 2*t;
            *(float2*)&P[(size_t)r*256 + c]     = make_float2(acc[mt][nt][0], acc[mt][nt][1]);
            *(float2*)&P[(size_t)(r+8)*256 + c] = make_float2(acc[mt][nt][2], acc[mt][nt][3]);
        }
}

// ---------------- 8) combine split-K + renorm ----------------
__global__ void av_combine_kernel()
{
    int idx = blockIdx.x * 256 + threadIdx.x;      // float4 index
    int row = idx >> 6;
    float inv = g_rowinv[row];
    float4 p0 = *(float4*)&g_avp[(size_t)idx*4];
    float4 p1 = *(float4*)&g_avp[(size_t)B_*NS*SD + (size_t)idx*4];
    float4 o;
    o.x = (p0.x + p1.x) * inv;  o.y = (p0.y + p1.y) * inv;
    o.z = (p0.z + p1.z) * inv;  o.w = (p0.w + p1.w) * inv;
    *(float4*)&g_fattn[(size_t)idx*4] = o;
}

// ---------------- 9) H = relu([snF|fattn] @ Wf0^T) (tf32) ----------------
__global__ __launch_bounds__(256) void gemm_ff0_tf32()
{
    __shared__ unsigned As[128*36];
    __shared__ unsigned Bs[128*36];
    int tid = threadIdx.x, lane = tid & 31;
    int g = lane >> 2, t = lane & 3;
    int wid = tid >> 5, wr = (wid >> 1) * 32, wc = (wid & 1) * 64;
    int bm = blockIdx.x * 128, bn = blockIdx.y * 128;
    float acc[2][8][4] = {};
    gemm_nk(As, Bs, g_snF + (size_t)bm*256, 256, g_fattn + (size_t)bm*256, 256, 256,
            g_Wf0 + (size_t)bn*512, 512, 16, acc, wr, wc, g, t, tid);
    #pragma unroll
    for (int mt = 0; mt < 2; mt++)
        #pragma unroll
        for (int nt = 0; nt < 8; nt++) {
            int r = bm + wr + mt*16 + g, c = bn + wc + nt*8 + 2*t;
            *(float2*)&g_Hbuf[(size_t)r*1024 + c] =
                make_float2(fmaxf(acc[mt][nt][0],0.f), fmaxf(acc[mt][nt][1],0.f));
            *(float2*)&g_Hbuf[(size_t)(r+8)*1024 + c] =
                make_float2(fmaxf(acc[mt][nt][2],0.f), fmaxf(acc[mt][nt][3],0.f));
        }
}

// ---------------- 10) out = sigmoid([snA|fattn]@Wg^T)*fattn + H@Wf1^T ----------------
__global__ __launch_bounds__(256) void gemm_out_tf32(float* __restrict__ out)
{
    __shared__ unsigned As[128*36];
    __shared__ unsigned Bs[128*36];
    int tid = threadIdx.x, lane = tid & 31;
    int g = lane >> 2, t = lane & 3;
    int wid = tid >> 5, wr = (wid >> 1) * 32, wc = (wid & 1) * 64;
    int bm = blockIdx.x * 128, bn = blockIdx.y * 128;
    float acc[2][8][4] = {};
    // pass 1: gate logits
    gemm_nk(As, Bs, g_snA + (size_t)bm*256, 256, g_fattn + (size_t)bm*256, 256, 256,
            g_Wg + (size_t)bn*512, 512, 16, acc, wr, wc, g, t, tid);
    // transform in place: acc := fattn * sigmoid(acc)
    #pragma unroll
    for (int mt = 0; mt < 2; mt++)
        #pragma unroll
        for (int nt = 0; nt < 8; nt++) {
            int r = bm + wr + mt*16 + g, c = bn + wc + nt*8 + 2*t;
            float2 f0 = *(const float2*)&g_fattn[(size_t)r*256 + c];
            float2 f1 = *(const float2*)&g_fattn[(size_t)(r+8)*256 + c];
            acc[mt][nt][0] = f0.x / (1.f + __expf(-acc[mt][nt][0]));
            acc[mt][nt][1] = f0.y / (1.f + __expf(-acc[mt][nt][1]));
            acc[mt][nt][2] = f1.x / (1.f + __expf(-acc[mt][nt][2]));
            acc[mt][nt][3] = f1.y / (1.f + __expf(-acc[mt][nt][3]));
        }
    // pass 2: accumulate H @ Wf1^T on top
    gemm_nk(As, Bs, g_Hbuf + (size_t)bm*1024, 1024, g_Hbuf, 1024, 1<<30,
            g_Wf1 + (size_t)bn*1024, 1024, 32, acc, wr, wc, g, t, tid);
    #pragma unroll
    for (int mt = 0; mt < 2; mt++)
        #pragma unroll
        for (int nt = 0; nt < 8; nt++) {
            int r = bm + wr + mt*16 + g, c = bn + wc + nt*8 + 2*t;
            *(float2*)&out[(size_t)r*256 + c]     = make_float2(acc[mt][nt][0], acc[mt][nt][1]);
            *(float2*)&out[(size_t)(r+8)*256 + c] = make_float2(acc[mt][nt][2], acc[mt][nt][3]);
        }
}

// ---------------- host launcher ----------------
extern "C" void kernel_launch(void* const* d_in, const int* in_sizes, int n_in,
                              void* d_out, int out_size)
{
    const float *t, *slots, *kin, *vin;
    const float *w0[4], *b0[4], *w1[4], *b1[4], *wp[4], *bp[4];
    const float *lnAw, *lnAb, *lnFw, *lnFb;

    if (in_sizes[0] == 1) {
        t     = (const float*)d_in[0];
        slots = (const float*)d_in[1];
        kin   = (const float*)d_in[2];
        vin   = (const float*)d_in[3];
        for (int h = 0; h < 4; h++) {
            int base = 4 + h*6;
            w0[h] = (const float*)d_in[base+0];  b0[h] = (const float*)d_in[base+1];
            w1[h] = (const float*)d_in[base+2];  b1[h] = (const float*)d_in[base+3];
            wp[h] = (const float*)d_in[base+4];  bp[h] = (const float*)d_in[base+5];
        }
        lnAw = (const float*)d_in[28]; lnAb = (const float*)d_in[29];
        lnFw = (const float*)d_in[30]; lnFb = (const float*)d_in[31];
    } else {
        for (int h = 0; h < 4; h++) {
            int base = h*6;
            w0[h] = (const float*)d_in[base+0];  b0[h] = (const float*)d_in[base+1];
            w1[h] = (const float*)d_in[base+2];  b1[h] = (const float*)d_in[base+3];
            wp[h] = (const float*)d_in[base+4];  bp[h] = (const float*)d_in[base+5];
        }
        lnAw = (const float*)d_in[24]; lnAb = (const float*)d_in[25];
        lnFw = (const float*)d_in[26]; lnFb = (const float*)d_in[27];
        t     = (const float*)d_in[28];
        slots = (const float*)d_in[29];
        kin   = (const float*)d_in[30];
        vin   = (const float*)d_in[31];
    }

    tdw_kernel<<<4, 128>>>(t,
        w0[0],b0[0],w1[0],b1[0],  w0[1],b0[1],w1[1],b1[1],
        w0[2],b0[2],w1[2],b1[2],  w0[3],b0[3],w1[3],b1[3]);

    wmat_kernel<<< (SD*SD)/16,   256>>>(wp[0], bp[0], 0, SD*SD);
    wmat_kernel<<< (SD*2*SD)/16, 256>>>(wp[1], bp[1], 1, SD*2*SD);
    wmat_kernel<<< (MH*2*SD)/16, 256>>>(wp[2], bp[2], 2, MH*2*SD);
    wmat_kernel<<< (SD*MH)/16,   256>>>(wp[3], bp[3], 3, SD*MH);

    ln_kernel<<<(B_*NS)/8, 256>>>(slots, lnAw, lnAb, lnFw, lnFb);

    gemm_q_tf32<<<dim3(32, 2), 256>>>();

    static int attn_smem = (2*128*36 + 128*133) * 4;   // 104960 B
    cudaFuncSetAttribute(attn_qk_kernel, cudaFuncAttributeMaxDynamicSharedMemorySize, attn_smem);
    attn_qk_kernel<<<dim3(B_, NMT), 256, attn_smem>>>(kin);

    rowinv_kernel<<<B_, 128>>>();

    attn_av_kernel<<<dim3(B_, 2, 2), 256>>>(vin);

    av_combine_kernel<<<(B_*NS*SD/4)/256, 256>>>();

    gemm_ff0_tf32<<<dim3(32, 8), 256>>>();

    gemm_out_tf32<<<dim3(32, 2), 256>>>((float*)d_out);
}

// round 4
// speedup vs baseline: 3.0280x; 1.1594x over previous
#include <cuda_runtime.h>

// ---------------- problem dims ----------------
#define B_    32
#define NS    128
#define SD    256
#define NF    4096
#define MH    1024
#define NMT   32

// ---------------- device scratch ----------------
__device__ float g_h[4][64];
__device__ float g_Wq [SD*SD];
__device__ float g_Wg [SD*2*SD];
__device__ float g_Wf0[MH*2*SD];
__device__ float g_Wf1[SD*MH];
__device__ float g_snA[B_*NS*SD];
__device__ float g_snF[B_*NS*SD];
__device__ float g_q  [B_*NS*SD];
__device__ float g_att[(size_t)B_*NS*NF];       // 64 MB normalized probs (tf32-rounded)
__device__ float g_srow[B_*NMT*NS];
__device__ float g_rowinv[B_*NS];
__device__ float g_avp[(size_t)4*B_*NS*SD];     // split-K=4 partials
__device__ float g_fattn[B_*NS*SD];
__device__ float g_Hbuf[B_*NS*MH];

// ---------------- tf32 helpers ----------------
__device__ __forceinline__ unsigned f2tf(float f) {
    unsigned u;
    asm("cvt.rna.tf32.f32 %0, %1;" : "=r"(u) : "f"(f));
    return u;
}
__device__ __forceinline__ float rndtf(float f) { return __uint_as_float(f2tf(f)); }

__device__ __forceinline__ void mma8(float c[4], const unsigned a[4], const unsigned b[2]) {
    asm("mma.sync.aligned.m16n8k8.row.col.f32.tf32.tf32.f32 "
        "{%0,%1,%2,%3},{%4,%5,%6,%7},{%8,%9},{%0,%1,%2,%3};\n"
        : "+f"(c[0]), "+f"(c[1]), "+f"(c[2]), "+f"(c[3])
        : "r"(a[0]), "r"(a[1]), "r"(a[2]), "r"(a[3]), "r"(b[0]), "r"(b[1]));
}

#define SWZ(d) ((d) + (((d) >> 4) << 2))
#define CP_COMMIT asm volatile("cp.async.commit_group;\n" ::: "memory")
#define CP_WAIT0  asm volatile("cp.async.wait_group 0;\n" ::: "memory")
__device__ __forceinline__ void cpa16(unsigned d, const void* s) {
    asm volatile("cp.async.ca.shared.global [%0], [%1], 16;\n" :: "r"(d), "l"(s));
}

// ---- cp.async tile issue: BM x 32 floats, smem row stride 36 ----
template<int BM>
__device__ __forceinline__ void cpa_tile(unsigned sb, const float* a0, int lda0,
                                         const float* a1, int lda1, int split,
                                         int k0, int tid)
{
    if (BM == 128) {
        int r = tid >> 1, c0 = (tid & 1) * 16;
        #pragma unroll
        for (int j = 0; j < 4; j++) {
            int kc = c0 + 4*j, k = k0 + kc;
            const float* s = (k < split) ? a0 + (size_t)r*lda0 + k
                                         : a1 + (size_t)r*lda1 + (k - split);
            cpa16(sb + (unsigned)(r*36 + kc)*4u, s);
        }
    } else {  // BM == 64
        int r = tid >> 2, c0 = (tid & 3) * 8;
        #pragma unroll
        for (int j = 0; j < 2; j++) {
            int kc = c0 + 4*j, k = k0 + kc;
            const float* s = (k < split) ? a0 + (size_t)r*lda0 + k
                                         : a1 + (size_t)r*lda1 + (k - split);
            cpa16(sb + (unsigned)(r*36 + kc)*4u, s);
        }
    }
}

// ---- staging for K (row-major n x k) with cvt ----
__device__ __forceinline__ void ldg_rm(float4 p[4], const float* src, int ld,
                                       int k0, int tid) {
    int r = tid >> 1, c0 = (tid & 1) * 16;
    const float* p0 = src + (size_t)r * ld + k0 + c0;
    #pragma unroll
    for (int j = 0; j < 4; j++) p[j] = *(const float4*)(p0 + 4*j);
}
__device__ __forceinline__ void sts_rm(unsigned* S, const float4 p[4], int tid) {
    int r = tid >> 1, c0 = (tid & 1) * 16;
    #pragma unroll
    for (int j = 0; j < 4; j++) {
        uint4 u;
        u.x = f2tf(p[j].x); u.y = f2tf(p[j].y);
        u.z = f2tf(p[j].z); u.w = f2tf(p[j].w);
        *(uint4*)&S[r*36 + c0 + 4*j] = u;
    }
}
// ---- staging for V (k-major 32 x 128) with cvt + swizzle ----
__device__ __forceinline__ void ldg_kn(float4 p[4], const float* src, int ld,
                                       int k0, int tid) {
    int m = tid >> 3, dg = (tid & 7) * 16;
    const float* p0 = src + (size_t)(k0 + m) * ld + dg;
    #pragma unroll
    for (int j = 0; j < 4; j++) p[j] = *(const float4*)(p0 + 4*j);
}
__device__ __forceinline__ void sts_kn(unsigned* S, const float4 p[4], int tid) {
    int m = tid >> 3, dg = (tid & 7) * 16;
    #pragma unroll
    for (int j = 0; j < 4; j++) {
        int d = dg + 4*j;
        uint4 u;
        u.x = f2tf(p[j].x); u.y = f2tf(p[j].y);
        u.z = f2tf(p[j].z); u.w = f2tf(p[j].w);
        *(uint4*)&S[m*168 + SWZ(d)] = u;
    }
}

// ---- inner compute: one BK=32 chunk, B in [n][k] layout ----
template<int MT>
__device__ __forceinline__ void comp_nk(const unsigned* As, const unsigned* Bs,
                                        float acc[][8][4], int wr, int wc, int g, int t)
{
    #pragma unroll
    for (int ks = 0; ks < 4; ks++) {
        int kk = ks * 8 + t;
        unsigned a[MT][4];
        #pragma unroll
        for (int mt = 0; mt < MT; mt++) {
            int r = wr + mt*16 + g;
            a[mt][0] = As[r*36 + kk];
            a[mt][1] = As[(r+8)*36 + kk];
            a[mt][2] = As[r*36 + kk + 4];
            a[mt][3] = As[(r+8)*36 + kk + 4];
        }
        #pragma unroll
        for (int nt = 0; nt < 8; nt++) {
            int n = wc + nt*8 + g;
            unsigned b[2];
            b[0] = Bs[n*36 + kk];
            b[1] = Bs[n*36 + kk + 4];
            #pragma unroll
            for (int mt = 0; mt < MT; mt++) mma8(acc[mt][nt], a[mt], b);
        }
    }
}
// ---- inner compute: B in [k][n] swizzled layout (AV) ----
__device__ __forceinline__ void comp_kn(const unsigned* As, const unsigned* Bs,
                                        float acc[][8][4], int wr, int wc, int g, int t)
{
    #pragma unroll
    for (int ks = 0; ks < 4; ks++) {
        int kk = ks * 8 + t;
        unsigned a[2][4];
        #pragma unroll
        for (int mt = 0; mt < 2; mt++) {
            int r = wr + mt*16 + g;
            a[mt][0] = As[r*36 + kk];
            a[mt][1] = As[(r+8)*36 + kk];
            a[mt][2] = As[r*36 + kk + 4];
            a[mt][3] = As[(r+8)*36 + kk + 4];
        }
        #pragma unroll
        for (int nt = 0; nt < 8; nt++) {
            int n = wc + nt*8 + g;
            unsigned b[2];
            b[0] = Bs[kk*168 + SWZ(n)];
            b[1] = Bs[(kk+4)*168 + SWZ(n)];
            #pragma unroll
            for (int mt = 0; mt < 2; mt++) mma8(acc[mt][nt], a[mt], b);
        }
    }
}

// ---- full all-async double-buffered GEMM loop (pre-rounded operands) ----
template<int MT>
__device__ __forceinline__ void gemm_async(unsigned* sm, unsigned sbase,
    const float* a0, int lda0, const float* a1, int lda1, int split,
    const float* b, int ldb, int nchunks,
    float acc[][8][4], int wr, int wc, int g, int t, int tid)
{
    const int ASZ = MT * 64 * 36;
    unsigned* A[2]  = {sm, sm + ASZ};
    unsigned* Bs[2] = {sm + 2*ASZ, sm + 2*ASZ + 128*36};
    unsigned aoff[2] = {sbase, sbase + (unsigned)ASZ*4u};
    unsigned boff[2] = {sbase + (unsigned)2*ASZ*4u, sbase + (unsigned)(2*ASZ + 128*36)*4u};
    cpa_tile<MT*64>(aoff[0], a0, lda0, a1, lda1, split, 0, tid);
    cpa_tile<128>(boff[0], b, ldb, b, ldb, 1 << 30, 0, tid);
    CP_COMMIT;
    for (int c = 0; c < nchunks; c++) {
        CP_WAIT0; __syncthreads();
        if (c + 1 < nchunks) {
            cpa_tile<MT*64>(aoff[(c+1)&1], a0, lda0, a1, lda1, split, (c+1)*32, tid);
            cpa_tile<128>(boff[(c+1)&1], b, ldb, b, ldb, 1 << 30, (c+1)*32, tid);
            CP_COMMIT;
        }
        comp_nk<MT>(A[c&1], Bs[c&1], acc, wr, wc, g, t);
    }
    __syncthreads();
}

// ---------------- 1) time-dependent weight MLP heads ----------------
__global__ void tdw_kernel(const float* t,
    const float* qw0,const float* qb0,const float* qw1,const float* qb1,
    const float* gw0,const float* gb0,const float* gw1,const float* gb1,
    const float* f0w0,const float* f0b0,const float* f0w1,const float* f0b1,
    const float* f1w0,const float* f1b0,const float* f1w1,const float* f1b1)
{
    __shared__ float emb[257];
    __shared__ float h0[64];
    const float* w0s[4] = {qw0,gw0,f0w0,f1w0};
    const float* b0s[4] = {qb0,gb0,f0b0,f1b0};
    const float* w1s[4] = {qw1,gw1,f0w1,f1w1};
    const float* b1s[4] = {qb1,gb1,f0b1,f1b1};
    int head = blockIdx.x;
    int tid  = threadIdx.x;
    float tv = t[0];
    const float C = -9.210340371976184f / 128.0f;
    for (int j = tid; j < 257; j += blockDim.x) {
        float e;
        if (j == 0)        e = tv;
        else if (j <= 128) e = sinf(C * (float)(j-1)   * tv);
        else               e = cosf(C * (float)(j-129) * tv);
        emb[j] = e;
    }
    __syncthreads();
    int warp = tid >> 5, lane = tid & 31;
    const float* w0 = w0s[head];
    for (int r = warp; r < 64; r += 4) {
        float s = 0.f;
        for (int j = lane; j < 257; j += 32) s += w0[r*257 + j] * emb[j];
        #pragma unroll
        for (int o = 16; o; o >>= 1) s += __shfl_xor_sync(0xffffffffu, s, o);
        if (lane == 0) { s += b0s[head][r]; h0[r] = s / (1.f + expf(-s)); }
    }
    __syncthreads();
    if (tid < 64) {
        const float* w1 = w1s[head];
        float s = 0.f;
        #pragma unroll 8
        for (int j = 0; j < 64; j++) s += w1[tid*64 + j] * h0[j];
        s += b1s[head][tid];
        g_h[head][tid] = s / (1.f + expf(-s));
    }
}

// ---------------- 2) materialize all W = wp @ h + bp (merged, 4 rows/warp) ----------------
__global__ void wmat_kernel(const float* __restrict__ wp_q,  const float* __restrict__ bp_q,
                            const float* __restrict__ wp_g,  const float* __restrict__ bp_g,
                            const float* __restrict__ wp_f0, const float* __restrict__ bp_f0,
                            const float* __restrict__ wp_f1, const float* __restrict__ bp_f1)
{
    int gwarp = (blockIdx.x * 256 + threadIdx.x) >> 5;
    int lane  = threadIdx.x & 31;
    int rl = lane >> 3, sub = lane & 7;
    int r4 = gwarp * 4 + rl;
    const float* wp; const float* bp; float* W; int r; int which;
    if (r4 < 65536)       { wp = wp_q;  bp = bp_q;  W = g_Wq;  r = r4;          which = 0; }
    else if (r4 < 196608) { wp = wp_g;  bp = bp_g;  W = g_Wg;  r = r4 - 65536;  which = 1; }
    else if (r4 < 720896) { wp = wp_f0; bp = bp_f0; W = g_Wf0; r = r4 - 196608; which = 2; }
    else                  { wp = wp_f1; bp = bp_f1; W = g_Wf1; r = r4 - 720896; which = 3; }
    float4 h0 = *(const float4*)&g_h[which][sub*8];
    float4 h1 = *(const float4*)&g_h[which][sub*8 + 4];
    float4 a  = *(const float4*)&wp[(size_t)r*64 + sub*8];
    float4 bb = *(const float4*)&wp[(size_t)r*64 + sub*8 + 4];
    float p = a.x*h0.x + a.y*h0.y + a.z*h0.z + a.w*h0.w
            + bb.x*h1.x + bb.y*h1.y + bb.z*h1.z + bb.w*h1.w;
    p += __shfl_down_sync(0xffffffffu, p, 4);
    p += __shfl_down_sync(0xffffffffu, p, 2);
    p += __shfl_down_sync(0xffffffffu, p, 1);
    if (sub == 0) W[r] = rndtf(p + bp[r]);
}

// ---------------- 3) dual LayerNorm (outputs tf32-rounded) ----------------
__global__ void ln_kernel(const float* __restrict__ slots,
                          const float* __restrict__ aw, const float* __restrict__ ab,
                          const float* __restrict__ fw, const float* __restrict__ fb)
{
    int warp = threadIdx.x >> 5, lane = threadIdx.x & 31;
    int row  = blockIdx.x * 8 + warp;
    const float* x = slots + (size_t)row * 256;
    float4 x0 = *(const float4*)&x[lane*4];
    float4 x1 = *(const float4*)&x[128 + lane*4];
    float s = x0.x+x0.y+x0.z+x0.w + x1.x+x1.y+x1.z+x1.w;
    #pragma unroll
    for (int o = 16; o; o >>= 1) s += __shfl_xor_sync(0xffffffffu, s, o);
    float mu = s * (1.f/256.f);
    float d, q = 0.f;
    d = x0.x-mu; q += d*d;  d = x0.y-mu; q += d*d;
    d = x0.z-mu; q += d*d;  d = x0.w-mu; q += d*d;
    d = x1.x-mu; q += d*d;  d = x1.y-mu; q += d*d;
    d = x1.z-mu; q += d*d;  d = x1.w-mu; q += d*d;
    #pragma unroll
    for (int o = 16; o; o >>= 1) q += __shfl_xor_sync(0xffffffffu, q, o);
    float rstd = rsqrtf(q * (1.f/256.f) + 1e-5f);

    float4 aw0 = *(const float4*)&aw[lane*4],  aw1 = *(const float4*)&aw[128+lane*4];
    float4 ab0 = *(const float4*)&ab[lane*4],  ab1 = *(const float4*)&ab[128+lane*4];
    float4 fw0 = *(const float4*)&fw[lane*4],  fw1 = *(const float4*)&fw[128+lane*4];
    float4 fb0 = *(const float4*)&fb[lane*4],  fb1 = *(const float4*)&fb[128+lane*4];

    float4 yA0, yA1, yF0, yF1;
    yA0.x = rndtf((x0.x-mu)*rstd*aw0.x + ab0.x);  yA0.y = rndtf((x0.y-mu)*rstd*aw0.y + ab0.y);
    yA0.z = rndtf((x0.z-mu)*rstd*aw0.z + ab0.z);  yA0.w = rndtf((x0.w-mu)*rstd*aw0.w + ab0.w);
    yA1.x = rndtf((x1.x-mu)*rstd*aw1.x + ab1.x);  yA1.y = rndtf((x1.y-mu)*rstd*aw1.y + ab1.y);
    yA1.z = rndtf((x1.z-mu)*rstd*aw1.z + ab1.z);  yA1.w = rndtf((x1.w-mu)*rstd*aw1.w + ab1.w);
    yF0.x = rndtf((x0.x-mu)*rstd*fw0.x + fb0.x);  yF0.y = rndtf((x0.y-mu)*rstd*fw0.y + fb0.y);
    yF0.z = rndtf((x0.z-mu)*rstd*fw0.z + fb0.z);  yF0.w = rndtf((x0.w-mu)*rstd*fw0.w + fb0.w);
    yF1.x = rndtf((x1.x-mu)*rstd*fw1.x + fb1.x);  yF1.y = rndtf((x1.y-mu)*rstd*fw1.y + fb1.y);
    yF1.z = rndtf((x1.z-mu)*rstd*fw1.z + fb1.z);  yF1.w = rndtf((x1.w-mu)*rstd*fw1.w + fb1.w);

    *(float4*)&g_snA[(size_t)row*256 + lane*4]       = yA0;
    *(float4*)&g_snA[(size_t)row*256 + 128 + lane*4] = yA1;
    *(float4*)&g_snF[(size_t)row*256 + lane*4]       = yF0;
    *(float4*)&g_snF[(size_t)row*256 + 128 + lane*4] = yF1;
}

// ---------------- 4) q = snA @ Wq^T (BM=64, all-async) ----------------
__global__ __launch_bounds__(256) void gemm_q_tf32()
{
    extern __shared__ unsigned sm[];
    unsigned sbase = (unsigned)__cvta_generic_to_shared(sm);
    int tid = threadIdx.x, lane = tid & 31;
    int g = lane >> 2, t = lane & 3;
    int wid = tid >> 5, wr = (wid >> 1) * 16, wc = (wid & 1) * 64;
    int bm = blockIdx.x * 64, bn = blockIdx.y * 128;
    float acc[1][8][4] = {};
    gemm_async<1>(sm, sbase, g_snA + (size_t)bm*256, 256, g_snA, 256, 1<<30,
                  g_Wq + (size_t)bn*256, 256, 8, acc, wr, wc, g, t, tid);
    #pragma unroll
    for (int nt = 0; nt < 8; nt++) {
        int r = bm + wr + g, c = bn + wc + nt*8 + 2*t;
        *(float2*)&g_q[(size_t)r*256 + c]     = make_float2(rndtf(acc[0][nt][0]), rndtf(acc[0][nt][1]));
        *(float2*)&g_q[(size_t)(r+8)*256 + c] = make_float2(rndtf(acc[0][nt][2]), rndtf(acc[0][nt][3]));
    }
}

// ---------------- 5) QK^T + softmax(tile-local) → att probs ----------------
__global__ __launch_bounds__(256) void attn_qk_kernel(const float* __restrict__ Kin)
{
    extern __shared__ unsigned sm[];
    unsigned sbase = (unsigned)__cvta_generic_to_shared(sm);
    unsigned* A[2]  = {sm, sm + 128*36};
    unsigned* Bs[2] = {sm + 2*128*36, sm + 3*128*36};
    unsigned aoff[2] = {sbase, sbase + 128*36*4};
    float* L = (float*)sm;                 // [128][133] aliases buffers (used after loop)
    int b = blockIdx.x, mt_ = blockIdx.y;
    int tid = threadIdx.x, lane = tid & 31;
    int g = lane >> 2, t = lane & 3;
    int wid = tid >> 5, wr = (wid >> 1) * 32, wc = (wid & 1) * 64;
    const float* Q  = g_q + (size_t)b*128*256;
    const float* Kb = Kin + ((size_t)b*NF + mt_*128)*256;
    float acc[2][8][4] = {};
    float4 pb[4];
    cpa_tile<128>(aoff[0], Q, 256, Q, 256, 1<<30, 0, tid);
    CP_COMMIT;
    ldg_rm(pb, Kb, 256, 0, tid);
    for (int c = 0; c < 8; c++) {
        sts_rm(Bs[c&1], pb, tid);
        CP_WAIT0; __syncthreads();
        if (c + 1 < 8) {
            cpa_tile<128>(aoff[(c+1)&1], Q, 256, Q, 256, 1<<30, (c+1)*32, tid);
            CP_COMMIT;
            ldg_rm(pb, Kb, 256, (c+1)*32, tid);
        }
        comp_nk<2>(A[c&1], Bs[c&1], acc, wr, wc, g, t);
    }
    __syncthreads();
    const float scale = 0.0625f;
    #pragma unroll
    for (int mt = 0; mt < 2; mt++)
        #pragma unroll
        for (int nt = 0; nt < 8; nt++) {
            int r = wr + mt*16 + g, c = wc + nt*8 + 2*t;
            L[r*133 + c]       = acc[mt][nt][0]*scale;
            L[r*133 + c + 1]   = acc[mt][nt][1]*scale;
            L[(r+8)*133 + c]   = acc[mt][nt][2]*scale;
            L[(r+8)*133 + c+1] = acc[mt][nt][3]*scale;
        }
    __syncthreads();
    if (tid < 128) {                   // exact softmax over slots (rows), per column
        int m = tid;
        float mx = -1e30f;
        #pragma unroll 4
        for (int n = 0; n < 128; n++) mx = fmaxf(mx, L[n*133 + m]);
        float s = 0.f;
        #pragma unroll 4
        for (int n = 0; n < 128; n++) {
            float e = __expf(L[n*133 + m] - mx);
            L[n*133 + m] = e;  s += e;
        }
        float inv = 1.f / s;
        #pragma unroll 4
        for (int n = 0; n < 128; n++) L[n*133 + m] *= inv;
    }
    __syncthreads();
    if (tid < 128) {                   // per-slot partial sums over features
        int n = tid; float rs = 0.f;
        #pragma unroll 4
        for (int m = 0; m < 128; m++) rs += L[n*133 + m];
        g_srow[(b*NMT + mt_)*128 + n] = rs;
    }
    // write normalized probs (tf32-rounded)
    int n = tid >> 1, mh = (tid & 1) * 64;
    float* dst = g_att + ((size_t)b*128 + n)*NF + mt_*128 + mh;
    #pragma unroll
    for (int j = 0; j < 16; j++) {
        float4 v;
        v.x = rndtf(L[n*133 + mh + 4*j]);     v.y = rndtf(L[n*133 + mh + 4*j + 1]);
        v.z = rndtf(L[n*133 + mh + 4*j + 2]); v.w = rndtf(L[n*133 + mh + 4*j + 3]);
        *(float4*)(dst + 4*j) = v;
    }
}

// ---------------- 6) row-sum reduce → 1/(s+eps) ----------------
__global__ void rowinv_kernel()
{
    int b = blockIdx.x, n = threadIdx.x;
    float s = 0.f;
    #pragma unroll 8
    for (int mt = 0; mt < NMT; mt++) s += g_srow[(b*NMT + mt)*128 + n];
    g_rowinv[b*128 + n] = 1.f / (s + 1e-8f);
}

// ---------------- 7) att @ V (split-K=4) ----------------
__global__ __launch_bounds__(256) void attn_av_kernel(const float* __restrict__ Vin)
{
    extern __shared__ unsigned sm[];
    unsigned sbase = (unsigned)__cvta_generic_to_shared(sm);
    unsigned* A[2]  = {sm, sm + 128*36};
    unsigned* Bs[2] = {sm + 2*128*36, sm + 2*128*36 + 32*168};
    unsigned aoff[2] = {sbase, sbase + 128*36*4};
    int b = blockIdx.x, dt = blockIdx.y, ks_ = blockIdx.z;
    int tid = threadIdx.x, lane = tid & 31;
    int g = lane >> 2, t = lane & 3;
    int wid = tid >> 5, wr = (wid >> 1) * 32, wc = (wid & 1) * 64;
    const float* Ap = g_att + (size_t)b*128*NF + ks_*1024;
    const float* Bv = Vin + ((size_t)b*NF + ks_*1024)*256 + dt*128;
    float acc[2][8][4] = {};
    float4 pb[4];
    cpa_tile<128>(aoff[0], Ap, NF, Ap, NF, 1<<30, 0, tid);
    CP_COMMIT;
    ldg_kn(pb, Bv, 256, 0, tid);
    for (int c = 0; c < 32; c++) {
        sts_kn(Bs[c&1], pb, tid);
        CP_WAIT0; __syncthreads();
        if (c + 1 < 32) {
            cpa_tile<128>(aoff[(c+1)&1], Ap, NF, Ap, NF, 1<<30, (c+1)*32, tid);
            CP_COMMIT;
            ldg_kn(pb, Bv, 256, (c+1)*32, tid);
        }
        comp_kn(A[c&1], Bs[c&1], acc, wr, wc, g, t);
    }
    float* P = g_avp + ((size_t)ks_*B_ + b)*128*256 + dt*128;
    #pragma unroll
    for (int mt = 0; mt < 2; mt++)
        #pragma unroll
        for (int nt = 0; nt < 8; nt++) {
            int r = wr + mt*16 + g, c = wc + nt*8 + 2*t;
            *(float2*)&P[(size_t)r*256 + c]     = make_float2(acc[mt][nt][0], acc[mt][nt][1]);
            *(float2*)&P[(size_t)(r+8)*256 + c] = make_float2(acc[mt][nt][2], acc[mt][nt][3]);
        }
}

// ---------------- 8) combine split-K partials + renorm (tf32-rounded) ----------------
__global__ void av_combine_kernel()
{
    int idx = blockIdx.x * 256 + threadIdx.x;      // float4 index
    int row = idx >> 6;
    float inv = g_rowinv[row];
    const size_t STR = (size_t)B_*NS*SD;
    float4 p0 = *(float4*)&g_avp[(size_t)idx*4];
    float4 p1 = *(float4*)&g_avp[STR   + (size_t)idx*4];
    float4 p2 = *(float4*)&g_avp[2*STR + (size_t)idx*4];
    float4 p3 = *(float4*)&g_avp[3*STR + (size_t)idx*4];
    float4 o;
    o.x = rndtf((p0.x + p1.x + p2.x + p3.x) * inv);
    o.y = rndtf((p0.y + p1.y + p2.y + p3.y) * inv);
    o.z = rndtf((p0.z + p1.z + p2.z + p3.z) * inv);
    o.w = rndtf((p0.w + p1.w + p2.w + p3.w) * inv);
    *(float4*)&g_fattn[(size_t)idx*4] = o;
}

// ---------------- 9) H = relu([snF|fattn] @ Wf0^T) ----------------
__global__ __launch_bounds__(256) void gemm_ff0_tf32()
{
    extern __shared__ unsigned sm[];
    unsigned sbase = (unsigned)__cvta_generic_to_shared(sm);
    int tid = threadIdx.x, lane = tid & 31;
    int g = lane >> 2, t = lane & 3;
    int wid = tid >> 5, wr = (wid >> 1) * 32, wc = (wid & 1) * 64;
    int bm = blockIdx.x * 128, bn = blockIdx.y * 128;
    float acc[2][8][4] = {};
    gemm_async<2>(sm, sbase, g_snF + (size_t)bm*256, 256, g_fattn + (size_t)bm*256, 256, 256,
                  g_Wf0 + (size_t)bn*512, 512, 16, acc, wr, wc, g, t, tid);
    #pragma unroll
    for (int mt = 0; mt < 2; mt++)
        #pragma unroll
        for (int nt = 0; nt < 8; nt++) {
            int r = bm + wr + mt*16 + g, c = bn + wc + nt*8 + 2*t;
            *(float2*)&g_Hbuf[(size_t)r*1024 + c] =
                make_float2(rndtf(fmaxf(acc[mt][nt][0],0.f)), rndtf(fmaxf(acc[mt][nt][1],0.f)));
            *(float2*)&g_Hbuf[(size_t)(r+8)*1024 + c] =
                make_float2(rndtf(fmaxf(acc[mt][nt][2],0.f)), rndtf(fmaxf(acc[mt][nt][3],0.f)));
        }
}

// ---------------- 10) out = sigmoid([snA|fattn]@Wg^T)*fattn + H@Wf1^T (BM=64) ----------------
__global__ __launch_bounds__(256) void gemm_out_tf32(float* __restrict__ out)
{
    extern __shared__ unsigned sm[];
    unsigned sbase = (unsigned)__cvta_generic_to_shared(sm);
    int tid = threadIdx.x, lane = tid & 31;
    int g = lane >> 2, t = lane & 3;
    int wid = tid >> 5, wr = (wid >> 1) * 16, wc = (wid & 1) * 64;
    int bm = blockIdx.x * 64, bn = blockIdx.y * 128;
    float acc[1][8][4] = {};
    // pass 1: gate logits
    gemm_async<1>(sm, sbase, g_snA + (size_t)bm*256, 256, g_fattn + (size_t)bm*256, 256, 256,
                  g_Wg + (size_t)bn*512, 512, 16, acc, wr, wc, g, t, tid);
    // transform in place: acc := fattn * sigmoid(acc)
    #pragma unroll
    for (int nt = 0; nt < 8; nt++) {
        int r = bm + wr + g, c = bn + wc + nt*8 + 2*t;
        float2 f0 = *(const float2*)&g_fattn[(size_t)r*256 + c];
        float2 f1 = *(const float2*)&g_fattn[(size_t)(r+8)*256 + c];
        acc[0][nt][0] = f0.x / (1.f + __expf(-acc[0][nt][0]));
        acc[0][nt][1] = f0.y / (1.f + __expf(-acc[0][nt][1]));
        acc[0][nt][2] = f1.x / (1.f + __expf(-acc[0][nt][2]));
        acc[0][nt][3] = f1.y / (1.f + __expf(-acc[0][nt][3]));
    }
    // pass 2: accumulate H @ Wf1^T on top
    gemm_async<1>(sm, sbase, g_Hbuf + (size_t)bm*1024, 1024, g_Hbuf, 1024, 1<<30,
                  g_Wf1 + (size_t)bn*1024, 1024, 32, acc, wr, wc, g, t, tid);
    #pragma unroll
    for (int nt = 0; nt < 8; nt++) {
        int r = bm + wr + g, c = bn + wc + nt*8 + 2*t;
        *(float2*)&out[(size_t)r*256 + c]     = make_float2(acc[0][nt][0], acc[0][nt][1]);
        *(float2*)&out[(size_t)(r+8)*256 + c] = make_float2(acc[0][nt][2], acc[0][nt][3]);
    }
}

// ---------------- host launcher ----------------
extern "C" void kernel_launch(void* const* d_in, const int* in_sizes, int n_in,
                              void* d_out, int out_size)
{
    const float *t, *slots, *kin, *vin;
    const float *w0[4], *b0[4], *w1[4], *b1[4], *wp[4], *bp[4];
    const float *lnAw, *lnAb, *lnFw, *lnFb;

    if (in_sizes[0] == 1) {
        t     = (const float*)d_in[0];
        slots = (const float*)d_in[1];
        kin   = (const float*)d_in[2];
        vin   = (const float*)d_in[3];
        for (int h = 0; h < 4; h++) {
            int base = 4 + h*6;
            w0[h] = (const float*)d_in[base+0];  b0[h] = (const float*)d_in[base+1];
            w1[h] = (const float*)d_in[base+2];  b1[h] = (const float*)d_in[base+3];
            wp[h] = (const float*)d_in[base+4];  bp[h] = (const float*)d_in[base+5];
        }
        lnAw = (const float*)d_in[28]; lnAb = (const float*)d_in[29];
        lnFw = (const float*)d_in[30]; lnFb = (const float*)d_in[31];
    } else {
        for (int h = 0; h < 4; h++) {
            int base = h*6;
            w0[h] = (const float*)d_in[base+0];  b0[h] = (const float*)d_in[base+1];
            w1[h] = (const float*)d_in[base+2];  b1[h] = (const float*)d_in[base+3];
            wp[h] = (const float*)d_in[base+4];  bp[h] = (const float*)d_in[base+5];
        }
        lnAw = (const float*)d_in[24]; lnAb = (const float*)d_in[25];
        lnFw = (const float*)d_in[26]; lnFb = (const float*)d_in[27];
        t     = (const float*)d_in[28];
        slots = (const float*)d_in[29];
        kin   = (const float*)d_in[30];
        vin   = (const float*)d_in[31];
    }

    tdw_kernel<<<4, 128>>>(t,
        w0[0],b0[0],w1[0],b1[0],  w0[1],b0[1],w1[1],b1[1],
        w0[2],b0[2],w1[2],b1[2],  w0[3],b0[3],w1[3],b1[3]);

    wmat_kernel<<<30720, 256>>>(wp[0],bp[0], wp[1],bp[1], wp[2],bp[2], wp[3],bp[3]);

    ln_kernel<<<(B_*NS)/8, 256>>>(slots, lnAw, lnAb, lnFw, lnFb);

    const int SMEM_64  = 2*(64*36 + 128*36)*4;     // 55296
    const int SMEM_128 = 2*(128*36 + 128*36)*4;    // 73728
    const int SMEM_AV  = (2*128*36 + 2*32*168)*4;  // 79872

    cudaFuncSetAttribute(gemm_q_tf32,   cudaFuncAttributeMaxDynamicSharedMemorySize, SMEM_64);
    gemm_q_tf32<<<dim3(64, 2), 256, SMEM_64>>>();

    cudaFuncSetAttribute(attn_qk_kernel, cudaFuncAttributeMaxDynamicSharedMemorySize, SMEM_128);
    attn_qk_kernel<<<dim3(B_, NMT), 256, SMEM_128>>>(kin);

    rowinv_kernel<<<B_, 128>>>();

    cudaFuncSetAttribute(attn_av_kernel, cudaFuncAttributeMaxDynamicSharedMemorySize, SMEM_AV);
    attn_av_kernel<<<dim3(B_, 2, 4), 256, SMEM_AV>>>(vin);

    av_combine_kernel<<<(B_*NS*SD/4)/256, 256>>>();

    cudaFuncSetAttribute(gemm_ff0_tf32, cudaFuncAttributeMaxDynamicSharedMemorySize, SMEM_128);
    gemm_ff0_tf32<<<dim3(32, 8), 256, SMEM_128>>>();

    cudaFuncSetAttribute(gemm_out_tf32, cudaFuncAttributeMaxDynamicSharedMemorySize, SMEM_64);
    gemm_out_tf32<<<dim3(64, 2), 256, SMEM_64>>>((float*)d_out);
}

// round 5
// speedup vs baseline: 3.0331x; 1.0017x over previous
#include <cuda_runtime.h>

// ---------------- problem dims ----------------
#define B_    32
#define NS    128
#define SD    256
#define NF    4096
#define MH    1024
#define NMT   32

// ---------------- device scratch ----------------
__device__ float g_h[4][64];
__device__ float g_Wq [SD*SD];
__device__ float g_Wg [SD*2*SD];
__device__ float g_Wf0[MH*2*SD];
__device__ float g_Wf1[SD*MH];
__device__ float g_snA[B_*NS*SD];
__device__ float g_snF[B_*NS*SD];
__device__ float g_q  [B_*NS*SD];
__device__ float g_att[(size_t)B_*NS*NF];       // 64 MB normalized probs (tf32-rounded)
__device__ float g_srow[B_*NMT*NS];
__device__ float g_rowinv[B_*NS];
__device__ float g_avp[(size_t)4*B_*NS*SD];     // split-K=4 partials
__device__ float g_fattn[B_*NS*SD];
__device__ float g_Hbuf[B_*NS*MH];

// ---------------- tf32 helpers ----------------
__device__ __forceinline__ unsigned f2tf(float f) {
    unsigned u;
    asm("cvt.rna.tf32.f32 %0, %1;" : "=r"(u) : "f"(f));
    return u;
}
__device__ __forceinline__ float rndtf(float f) { return __uint_as_float(f2tf(f)); }

__device__ __forceinline__ void mma8(float c[4], const unsigned a[4], const unsigned b[2]) {
    asm("mma.sync.aligned.m16n8k8.row.col.f32.tf32.tf32.f32 "
        "{%0,%1,%2,%3},{%4,%5,%6,%7},{%8,%9},{%0,%1,%2,%3};\n"
        : "+f"(c[0]), "+f"(c[1]), "+f"(c[2]), "+f"(c[3])
        : "r"(a[0]), "r"(a[1]), "r"(a[2]), "r"(a[3]), "r"(b[0]), "r"(b[1]));
}

#define SWZ(d) ((d) + (((d) >> 4) << 2))
#define CP_COMMIT asm volatile("cp.async.commit_group;\n" ::: "memory")
#define CP_WAIT0  asm volatile("cp.async.wait_group 0;\n" ::: "memory")
__device__ __forceinline__ void cpa16(unsigned d, const void* s) {
    asm volatile("cp.async.ca.shared.global [%0], [%1], 16;\n" :: "r"(d), "l"(s));
}

// ---- cp.async tile issue: BM x 32 floats, smem row stride 36 ----
template<int BM>
__device__ __forceinline__ void cpa_tile(unsigned sb, const float* a0, int lda0,
                                         const float* a1, int lda1, int split,
                                         int k0, int tid)
{
    if (BM == 128) {
        int r = tid >> 1, c0 = (tid & 1) * 16;
        #pragma unroll
        for (int j = 0; j < 4; j++) {
            int kc = c0 + 4*j, k = k0 + kc;
            const float* s = (k < split) ? a0 + (size_t)r*lda0 + k
                                         : a1 + (size_t)r*lda1 + (k - split);
            cpa16(sb + (unsigned)(r*36 + kc)*4u, s);
        }
    } else {  // BM == 64
        int r = tid >> 2, c0 = (tid & 3) * 8;
        #pragma unroll
        for (int j = 0; j < 2; j++) {
            int kc = c0 + 4*j, k = k0 + kc;
            const float* s = (k < split) ? a0 + (size_t)r*lda0 + k
                                         : a1 + (size_t)r*lda1 + (k - split);
            cpa16(sb + (unsigned)(r*36 + kc)*4u, s);
        }
    }
}

// ---- staging for K (row-major n x k) with cvt ----
__device__ __forceinline__ void ldg_rm(float4 p[4], const float* src, int ld,
                                       int k0, int tid) {
    int r = tid >> 1, c0 = (tid & 1) * 16;
    const float* p0 = src + (size_t)r * ld + k0 + c0;
    #pragma unroll
    for (int j = 0; j < 4; j++) p[j] = *(const float4*)(p0 + 4*j);
}
__device__ __forceinline__ void sts_rm(unsigned* S, const float4 p[4], int tid) {
    int r = tid >> 1, c0 = (tid & 1) * 16;
    #pragma unroll
    for (int j = 0; j < 4; j++) {
        uint4 u;
        u.x = f2tf(p[j].x); u.y = f2tf(p[j].y);
        u.z = f2tf(p[j].z); u.w = f2tf(p[j].w);
        *(uint4*)&S[r*36 + c0 + 4*j] = u;
    }
}
// ---- staging for V (k-major 32 x 128) with cvt + swizzle ----
__device__ __forceinline__ void ldg_kn(float4 p[4], const float* src, int ld,
                                       int k0, int tid) {
    int m = tid >> 3, dg = (tid & 7) * 16;
    const float* p0 = src + (size_t)(k0 + m) * ld + dg;
    #pragma unroll
    for (int j = 0; j < 4; j++) p[j] = *(const float4*)(p0 + 4*j);
}
__device__ __forceinline__ void sts_kn(unsigned* S, const float4 p[4], int tid) {
    int m = tid >> 3, dg = (tid & 7) * 16;
    #pragma unroll
    for (int j = 0; j < 4; j++) {
        int d = dg + 4*j;
        uint4 u;
        u.x = f2tf(p[j].x); u.y = f2tf(p[j].y);
        u.z = f2tf(p[j].z); u.w = f2tf(p[j].w);
        *(uint4*)&S[m*168 + SWZ(d)] = u;
    }
}

// ---- inner compute: one BK=32 chunk, B in [n][k] layout ----
template<int MT>
__device__ __forceinline__ void comp_nk(const unsigned* As, const unsigned* Bs,
                                        float acc[][8][4], int wr, int wc, int g, int t)
{
    #pragma unroll
    for (int ks = 0; ks < 4; ks++) {
        int kk = ks * 8 + t;
        unsigned a[MT][4];
        #pragma unroll
        for (int mt = 0; mt < MT; mt++) {
            int r = wr + mt*16 + g;
            a[mt][0] = As[r*36 + kk];
            a[mt][1] = As[(r+8)*36 + kk];
            a[mt][2] = As[r*36 + kk + 4];
            a[mt][3] = As[(r+8)*36 + kk + 4];
        }
        #pragma unroll
        for (int nt = 0; nt < 8; nt++) {
            int n = wc + nt*8 + g;
            unsigned b[2];
            b[0] = Bs[n*36 + kk];
            b[1] = Bs[n*36 + kk + 4];
            #pragma unroll
            for (int mt = 0; mt < MT; mt++) mma8(acc[mt][nt], a[mt], b);
        }
    }
}
// ---- inner compute: B in [k][n] swizzled layout (AV) ----
__device__ __forceinline__ void comp_kn(const unsigned* As, const unsigned* Bs,
                                        float acc[][8][4], int wr, int wc, int g, int t)
{
    #pragma unroll
    for (int ks = 0; ks < 4; ks++) {
        int kk = ks * 8 + t;
        unsigned a[2][4];
        #pragma unroll
        for (int mt = 0; mt < 2; mt++) {
            int r = wr + mt*16 + g;
            a[mt][0] = As[r*36 + kk];
            a[mt][1] = As[(r+8)*36 + kk];
            a[mt][2] = As[r*36 + kk + 4];
            a[mt][3] = As[(r+8)*36 + kk + 4];
        }
        #pragma unroll
        for (int nt = 0; nt < 8; nt++) {
            int n = wc + nt*8 + g;
            unsigned b[2];
            b[0] = Bs[kk*168 + SWZ(n)];
            b[1] = Bs[(kk+4)*168 + SWZ(n)];
            #pragma unroll
            for (int mt = 0; mt < 2; mt++) mma8(acc[mt][nt], a[mt], b);
        }
    }
}

// ---- full all-async double-buffered GEMM loop (pre-rounded operands) ----
template<int MT>
__device__ __forceinline__ void gemm_async(unsigned* sm, unsigned sbase,
    const float* a0, int lda0, const float* a1, int lda1, int split,
    const float* b, int ldb, int nchunks,
    float acc[][8][4], int wr, int wc, int g, int t, int tid)
{
    const int ASZ = MT * 64 * 36;
    unsigned* A[2]  = {sm, sm + ASZ};
    unsigned* Bs[2] = {sm + 2*ASZ, sm + 2*ASZ + 128*36};
    unsigned aoff[2] = {sbase, sbase + (unsigned)ASZ*4u};
    unsigned boff[2] = {sbase + (unsigned)2*ASZ*4u, sbase + (unsigned)(2*ASZ + 128*36)*4u};
    cpa_tile<MT*64>(aoff[0], a0, lda0, a1, lda1, split, 0, tid);
    cpa_tile<128>(boff[0], b, ldb, b, ldb, 1 << 30, 0, tid);
    CP_COMMIT;
    for (int c = 0; c < nchunks; c++) {
        CP_WAIT0; __syncthreads();
        if (c + 1 < nchunks) {
            cpa_tile<MT*64>(aoff[(c+1)&1], a0, lda0, a1, lda1, split, (c+1)*32, tid);
            cpa_tile<128>(boff[(c+1)&1], b, ldb, b, ldb, 1 << 30, (c+1)*32, tid);
            CP_COMMIT;
        }
        comp_nk<MT>(A[c&1], Bs[c&1], acc, wr, wc, g, t);
    }
    __syncthreads();
}

// ---------------- 1) time-dependent weight MLP heads ----------------
__global__ void tdw_kernel(const float* t,
    const float* qw0,const float* qb0,const float* qw1,const float* qb1,
    const float* gw0,const float* gb0,const float* gw1,const float* gb1,
    const float* f0w0,const float* f0b0,const float* f0w1,const float* f0b1,
    const float* f1w0,const float* f1b0,const float* f1w1,const float* f1b1)
{
    __shared__ float emb[257];
    __shared__ float h0[64];
    const float* w0s[4] = {qw0,gw0,f0w0,f1w0};
    const float* b0s[4] = {qb0,gb0,f0b0,f1b0};
    const float* w1s[4] = {qw1,gw1,f0w1,f1w1};
    const float* b1s[4] = {qb1,gb1,f0b1,f1b1};
    int head = blockIdx.x;
    int tid  = threadIdx.x;
    float tv = t[0];
    const float C = -9.210340371976184f / 128.0f;
    for (int j = tid; j < 257; j += blockDim.x) {
        float e;
        if (j == 0)        e = tv;
        else if (j <= 128) e = sinf(C * (float)(j-1)   * tv);
        else               e = cosf(C * (float)(j-129) * tv);
        emb[j] = e;
    }
    __syncthreads();
    int warp = tid >> 5, lane = tid & 31;
    const float* w0 = w0s[head];
    for (int r = warp; r < 64; r += 4) {
        float s = 0.f;
        for (int j = lane; j < 257; j += 32) s += w0[r*257 + j] * emb[j];
        #pragma unroll
        for (int o = 16; o; o >>= 1) s += __shfl_xor_sync(0xffffffffu, s, o);
        if (lane == 0) { s += b0s[head][r]; h0[r] = s / (1.f + expf(-s)); }
    }
    __syncthreads();
    if (tid < 64) {
        const float* w1 = w1s[head];
        float s = 0.f;
        #pragma unroll 8
        for (int j = 0; j < 64; j++) s += w1[tid*64 + j] * h0[j];
        s += b1s[head][tid];
        g_h[head][tid] = s / (1.f + expf(-s));
    }
}

// ---------------- 2) materialize all W = wp @ h + bp (merged, 4 rows/warp) ----------------
__global__ void wmat_kernel(const float* __restrict__ wp_q,  const float* __restrict__ bp_q,
                            const float* __restrict__ wp_g,  const float* __restrict__ bp_g,
                            const float* __restrict__ wp_f0, const float* __restrict__ bp_f0,
                            const float* __restrict__ wp_f1, const float* __restrict__ bp_f1)
{
    int gwarp = (blockIdx.x * 256 + threadIdx.x) >> 5;
    int lane  = threadIdx.x & 31;
    int rl = lane >> 3, sub = lane & 7;
    int r4 = gwarp * 4 + rl;
    const float* wp; const float* bp; float* W; int r; int which;
    if (r4 < 65536)       { wp = wp_q;  bp = bp_q;  W = g_Wq;  r = r4;          which = 0; }
    else if (r4 < 196608) { wp = wp_g;  bp = bp_g;  W = g_Wg;  r = r4 - 65536;  which = 1; }
    else if (r4 < 720896) { wp = wp_f0; bp = bp_f0; W = g_Wf0; r = r4 - 196608; which = 2; }
    else                  { wp = wp_f1; bp = bp_f1; W = g_Wf1; r = r4 - 720896; which = 3; }
    float4 h0 = *(const float4*)&g_h[which][sub*8];
    float4 h1 = *(const float4*)&g_h[which][sub*8 + 4];
    float4 a  = *(const float4*)&wp[(size_t)r*64 + sub*8];
    float4 bb = *(const float4*)&wp[(size_t)r*64 + sub*8 + 4];
    float p = a.x*h0.x + a.y*h0.y + a.z*h0.z + a.w*h0.w
            + bb.x*h1.x + bb.y*h1.y + bb.z*h1.z + bb.w*h1.w;
    p += __shfl_down_sync(0xffffffffu, p, 4);
    p += __shfl_down_sync(0xffffffffu, p, 2);
    p += __shfl_down_sync(0xffffffffu, p, 1);
    if (sub == 0) W[r] = rndtf(p + bp[r]);
}

// ---------------- 3) dual LayerNorm (outputs tf32-rounded) ----------------
__global__ void ln_kernel(const float* __restrict__ slots,
                          const float* __restrict__ aw, const float* __restrict__ ab,
                          const float* __restrict__ fw, const float* __restrict__ fb)
{
    int warp = threadIdx.x >> 5, lane = threadIdx.x & 31;
    int row  = blockIdx.x * 8 + warp;
    const float* x = slots + (size_t)row * 256;
    float4 x0 = *(const float4*)&x[lane*4];
    float4 x1 = *(const float4*)&x[128 + lane*4];
    float s = x0.x+x0.y+x0.z+x0.w + x1.x+x1.y+x1.z+x1.w;
    #pragma unroll
    for (int o = 16; o; o >>= 1) s += __shfl_xor_sync(0xffffffffu, s, o);
    float mu = s * (1.f/256.f);
    float d, q = 0.f;
    d = x0.x-mu; q += d*d;  d = x0.y-mu; q += d*d;
    d = x0.z-mu; q += d*d;  d = x0.w-mu; q += d*d;
    d = x1.x-mu; q += d*d;  d = x1.y-mu; q += d*d;
    d = x1.z-mu; q += d*d;  d = x1.w-mu; q += d*d;
    #pragma unroll
    for (int o = 16; o; o >>= 1) q += __shfl_xor_sync(0xffffffffu, q, o);
    float rstd = rsqrtf(q * (1.f/256.f) + 1e-5f);

    float4 aw0 = *(const float4*)&aw[lane*4],  aw1 = *(const float4*)&aw[128+lane*4];
    float4 ab0 = *(const float4*)&ab[lane*4],  ab1 = *(const float4*)&ab[128+lane*4];
    float4 fw0 = *(const float4*)&fw[lane*4],  fw1 = *(const float4*)&fw[128+lane*4];
    float4 fb0 = *(const float4*)&fb[lane*4],  fb1 = *(const float4*)&fb[128+lane*4];

    float4 yA0, yA1, yF0, yF1;
    yA0.x = rndtf((x0.x-mu)*rstd*aw0.x + ab0.x);  yA0.y = rndtf((x0.y-mu)*rstd*aw0.y + ab0.y);
    yA0.z = rndtf((x0.z-mu)*rstd*aw0.z + ab0.z);  yA0.w = rndtf((x0.w-mu)*rstd*aw0.w + ab0.w);
    yA1.x = rndtf((x1.x-mu)*rstd*aw1.x + ab1.x);  yA1.y = rndtf((x1.y-mu)*rstd*aw1.y + ab1.y);
    yA1.z = rndtf((x1.z-mu)*rstd*aw1.z + ab1.z);  yA1.w = rndtf((x1.w-mu)*rstd*aw1.w + ab1.w);
    yF0.x = rndtf((x0.x-mu)*rstd*fw0.x + fb0.x);  yF0.y = rndtf((x0.y-mu)*rstd*fw0.y + fb0.y);
    yF0.z = rndtf((x0.z-mu)*rstd*fw0.z + fb0.z);  yF0.w = rndtf((x0.w-mu)*rstd*fw0.w + fb0.w);
    yF1.x = rndtf((x1.x-mu)*rstd*fw1.x + fb1.x);  yF1.y = rndtf((x1.y-mu)*rstd*fw1.y + fb1.y);
    yF1.z = rndtf((x1.z-mu)*rstd*fw1.z + fb1.z);  yF1.w = rndtf((x1.w-mu)*rstd*fw1.w + fb1.w);

    *(float4*)&g_snA[(size_t)row*256 + lane*4]       = yA0;
    *(float4*)&g_snA[(size_t)row*256 + 128 + lane*4] = yA1;
    *(float4*)&g_snF[(size_t)row*256 + lane*4]       = yF0;
    *(float4*)&g_snF[(size_t)row*256 + 128 + lane*4] = yF1;
}

// ---------------- 4) q = snA @ Wq^T (BM=64, all-async) ----------------
__global__ __launch_bounds__(256) void gemm_q_tf32()
{
    extern __shared__ unsigned sm[];
    unsigned sbase = (unsigned)__cvta_generic_to_shared(sm);
    int tid = threadIdx.x, lane = tid & 31;
    int g = lane >> 2, t = lane & 3;
    int wid = tid >> 5, wr = (wid >> 1) * 16, wc = (wid & 1) * 64;
    int bm = blockIdx.x * 64, bn = blockIdx.y * 128;
    float acc[1][8][4] = {};
    gemm_async<1>(sm, sbase, g_snA + (size_t)bm*256, 256, g_snA, 256, 1<<30,
                  g_Wq + (size_t)bn*256, 256, 8, acc, wr, wc, g, t, tid);
    #pragma unroll
    for (int nt = 0; nt < 8; nt++) {
        int r = bm + wr + g, c = bn + wc + nt*8 + 2*t;
        *(float2*)&g_q[(size_t)r*256 + c]     = make_float2(rndtf(acc[0][nt][0]), rndtf(acc[0][nt][1]));
        *(float2*)&g_q[(size_t)(r+8)*256 + c] = make_float2(rndtf(acc[0][nt][2]), rndtf(acc[0][nt][3]));
    }
}

// ---------------- 5) QK^T + softmax(tile-local) → att probs ----------------
__global__ __launch_bounds__(256) void attn_qk_kernel(const float* __restrict__ Kin)
{
    extern __shared__ unsigned sm[];
    unsigned sbase = (unsigned)__cvta_generic_to_shared(sm);
    unsigned* A[2]  = {sm, sm + 128*36};
    unsigned* Bs[2] = {sm + 2*128*36, sm + 3*128*36};
    unsigned aoff[2] = {sbase, sbase + 128*36*4};
    float* L = (float*)sm;                 // [128][133] aliases buffers (used after loop)
    int b = blockIdx.x, mt_ = blockIdx.y;
    int tid = threadIdx.x, lane = tid & 31;
    int g = lane >> 2, t = lane & 3;
    int wid = tid >> 5, wr = (wid >> 1) * 32, wc = (wid & 1) * 64;
    const float* Q  = g_q + (size_t)b*128*256;
    const float* Kb = Kin + ((size_t)b*NF + mt_*128)*256;
    float acc[2][8][4] = {};
    float4 pb[4];
    cpa_tile<128>(aoff[0], Q, 256, Q, 256, 1<<30, 0, tid);
    CP_COMMIT;
    ldg_rm(pb, Kb, 256, 0, tid);
    for (int c = 0; c < 8; c++) {
        sts_rm(Bs[c&1], pb, tid);
        CP_WAIT0; __syncthreads();
        if (c + 1 < 8) {
            cpa_tile<128>(aoff[(c+1)&1], Q, 256, Q, 256, 1<<30, (c+1)*32, tid);
            CP_COMMIT;
            ldg_rm(pb, Kb, 256, (c+1)*32, tid);
        }
        comp_nk<2>(A[c&1], Bs[c&1], acc, wr, wc, g, t);
    }
    __syncthreads();
    const float scale = 0.0625f;
    #pragma unroll
    for (int mt = 0; mt < 2; mt++)
        #pragma unroll
        for (int nt = 0; nt < 8; nt++) {
            int r = wr + mt*16 + g, c = wc + nt*8 + 2*t;
            L[r*133 + c]       = acc[mt][nt][0]*scale;
            L[r*133 + c + 1]   = acc[mt][nt][1]*scale;
            L[(r+8)*133 + c]   = acc[mt][nt][2]*scale;
            L[(r+8)*133 + c+1] = acc[mt][nt][3]*scale;
        }
    __syncthreads();
    if (tid < 128) {                   // exact softmax over slots (rows), per column
        int m = tid;
        float mx = -1e30f;
        #pragma unroll 4
        for (int n = 0; n < 128; n++) mx = fmaxf(mx, L[n*133 + m]);
        float s = 0.f;
        #pragma unroll 4
        for (int n = 0; n < 128; n++) {
            float e = __expf(L[n*133 + m] - mx);
            L[n*133 + m] = e;  s += e;
        }
        float inv = 1.f / s;
        #pragma unroll 4
        for (int n = 0; n < 128; n++) L[n*133 + m] *= inv;
    }
    __syncthreads();
    if (tid < 128) {                   // per-slot partial sums over features
        int n = tid; float rs = 0.f;
        #pragma unroll 4
        for (int m = 0; m < 128; m++) rs += L[n*133 + m];
        g_srow[(b*NMT + mt_)*128 + n] = rs;
    }
    // write normalized probs (tf32-rounded)
    int n = tid >> 1, mh = (tid & 1) * 64;
    float* dst = g_att + ((size_t)b*128 + n)*NF + mt_*128 + mh;
    #pragma unroll
    for (int j = 0; j < 16; j++) {
        float4 v;
        v.x = rndtf(L[n*133 + mh + 4*j]);     v.y = rndtf(L[n*133 + mh + 4*j + 1]);
        v.z = rndtf(L[n*133 + mh + 4*j + 2]); v.w = rndtf(L[n*133 + mh + 4*j + 3]);
        *(float4*)(dst + 4*j) = v;
    }
}

// ---------------- 6) row-sum reduce → 1/(s+eps) ----------------
__global__ void rowinv_kernel()
{
    int b = blockIdx.x, n = threadIdx.x;
    float s = 0.f;
    #pragma unroll 8
    for (int mt = 0; mt < NMT; mt++) s += g_srow[(b*NMT + mt)*128 + n];
    g_rowinv[b*128 + n] = 1.f / (s + 1e-8f);
}

// ---------------- 7) att @ V (split-K=4) ----------------
__global__ __launch_bounds__(256) void attn_av_kernel(const float* __restrict__ Vin)
{
    extern __shared__ unsigned sm[];
    unsigned sbase = (unsigned)__cvta_generic_to_shared(sm);
    unsigned* A[2]  = {sm, sm + 128*36};
    unsigned* Bs[2] = {sm + 2*128*36, sm + 2*128*36 + 32*168};
    unsigned aoff[2] = {sbase, sbase + 128*36*4};
    int b = blockIdx.x, dt = blockIdx.y, ks_ = blockIdx.z;
    int tid = threadIdx.x, lane = tid & 31;
    int g = lane >> 2, t = lane & 3;
    int wid = tid >> 5, wr = (wid >> 1) * 32, wc = (wid & 1) * 64;
    const float* Ap = g_att + (size_t)b*128*NF + ks_*1024;
    const float* Bv = Vin + ((size_t)b*NF + ks_*1024)*256 + dt*128;
    float acc[2][8][4] = {};
    float4 pb[4];
    cpa_tile<128>(aoff[0], Ap, NF, Ap, NF, 1<<30, 0, tid);
    CP_COMMIT;
    ldg_kn(pb, Bv, 256, 0, tid);
    for (int c = 0; c < 32; c++) {
        sts_kn(Bs[c&1], pb, tid);
        CP_WAIT0; __syncthreads();
        if (c + 1 < 32) {
            cpa_tile<128>(aoff[(c+1)&1], Ap, NF, Ap, NF, 1<<30, (c+1)*32, tid);
            CP_COMMIT;
            ldg_kn(pb, Bv, 256, (c+1)*32, tid);
        }
        comp_kn(A[c&1], Bs[c&1], acc, wr, wc, g, t);
    }
    float* P = g_avp + ((size_t)ks_*B_ + b)*128*256 + dt*128;
    #pragma unroll
    for (int mt = 0; mt < 2; mt++)
        #pragma unroll
        for (int nt = 0; nt < 8; nt++) {
            int r = wr + mt*16 + g, c = wc + nt*8 + 2*t;
            *(float2*)&P[(size_t)r*256 + c]     = make_float2(acc[mt][nt][0], acc[mt][nt][1]);
            *(float2*)&P[(size_t)(r+8)*256 + c] = make_float2(acc[mt][nt][2], acc[mt][nt][3]);
        }
}

// ---------------- 8) combine split-K partials + renorm (tf32-rounded) ----------------
__global__ void av_combine_kernel()
{
    int idx = blockIdx.x * 256 + threadIdx.x;      // float4 index
    int row = idx >> 6;
    float inv = g_rowinv[row];
    const size_t STR = (size_t)B_*NS*SD;
    float4 p0 = *(float4*)&g_avp[(size_t)idx*4];
    float4 p1 = *(float4*)&g_avp[STR   + (size_t)idx*4];
    float4 p2 = *(float4*)&g_avp[2*STR + (size_t)idx*4];
    float4 p3 = *(float4*)&g_avp[3*STR + (size_t)idx*4];
    float4 o;
    o.x = rndtf((p0.x + p1.x + p2.x + p3.x) * inv);
    o.y = rndtf((p0.y + p1.y + p2.y + p3.y) * inv);
    o.z = rndtf((p0.z + p1.z + p2.z + p3.z) * inv);
    o.w = rndtf((p0.w + p1.w + p2.w + p3.w) * inv);
    *(float4*)&g_fattn[(size_t)idx*4] = o;
}

// ---------------- 9) H = relu([snF|fattn] @ Wf0^T) ----------------
__global__ __launch_bounds__(256) void gemm_ff0_tf32()
{
    extern __shared__ unsigned sm[];
    unsigned sbase = (unsigned)__cvta_generic_to_shared(sm);
    int tid = threadIdx.x, lane = tid & 31;
    int g = lane >> 2, t = lane & 3;
    int wid = tid >> 5, wr = (wid >> 1) * 32, wc = (wid & 1) * 64;
    int bm = blockIdx.x * 128, bn = blockIdx.y * 128;
    float acc[2][8][4] = {};
    gemm_async<2>(sm, sbase, g_snF + (size_t)bm*256, 256, g_fattn + (size_t)bm*256, 256, 256,
                  g_Wf0 + (size_t)bn*512, 512, 16, acc, wr, wc, g, t, tid);
    #pragma unroll
    for (int mt = 0; mt < 2; mt++)
        #pragma unroll
        for (int nt = 0; nt < 8; nt++) {
            int r = bm + wr + mt*16 + g, c = bn + wc + nt*8 + 2*t;
            *(float2*)&g_Hbuf[(size_t)r*1024 + c] =
                make_float2(rndtf(fmaxf(acc[mt][nt][0],0.f)), rndtf(fmaxf(acc[mt][nt][1],0.f)));
            *(float2*)&g_Hbuf[(size_t)(r+8)*1024 + c] =
                make_float2(rndtf(fmaxf(acc[mt][nt][2],0.f)), rndtf(fmaxf(acc[mt][nt][3],0.f)));
        }
}

// ---------------- 10) out = sigmoid([snA|fattn]@Wg^T)*fattn + H@Wf1^T (BM=64) ----------------
__global__ __launch_bounds__(256) void gemm_out_tf32(float* __restrict__ out)
{
    extern __shared__ unsigned sm[];
    unsigned sbase = (unsigned)__cvta_generic_to_shared(sm);
    int tid = threadIdx.x, lane = tid & 31;
    int g = lane >> 2, t = lane & 3;
    int wid = tid >> 5, wr = (wid >> 1) * 16, wc = (wid & 1) * 64;
    int bm = blockIdx.x * 64, bn = blockIdx.y * 128;
    float acc[1][8][4] = {};
    // pass 1: gate logits
    gemm_async<1>(sm, sbase, g_snA + (size_t)bm*256, 256, g_fattn + (size_t)bm*256, 256, 256,
                  g_Wg + (size_t)bn*512, 512, 16, acc, wr, wc, g, t, tid);
    // transform in place: acc := fattn * sigmoid(acc)
    #pragma unroll
    for (int nt = 0; nt < 8; nt++) {
        int r = bm + wr + g, c = bn + wc + nt*8 + 2*t;
        float2 f0 = *(const float2*)&g_fattn[(size_t)r*256 + c];
        float2 f1 = *(const float2*)&g_fattn[(size_t)(r+8)*256 + c];
        acc[0][nt][0] = f0.x / (1.f + __expf(-acc[0][nt][0]));
        acc[0][nt][1] = f0.y / (1.f + __expf(-acc[0][nt][1]));
        acc[0][nt][2] = f1.x / (1.f + __expf(-acc[0][nt][2]));
        acc[0][nt][3] = f1.y / (1.f + __expf(-acc[0][nt][3]));
    }
    // pass 2: accumulate H @ Wf1^T on top
    gemm_async<1>(sm, sbase, g_Hbuf + (size_t)bm*1024, 1024, g_Hbuf, 1024, 1<<30,
                  g_Wf1 + (size_t)bn*1024, 1024, 32, acc, wr, wc, g, t, tid);
    #pragma unroll
    for (int nt = 0; nt < 8; nt++) {
        int r = bm + wr + g, c = bn + wc + nt*8 + 2*t;
        *(float2*)&out[(size_t)r*256 + c]     = make_float2(acc[0][nt][0], acc[0][nt][1]);
        *(float2*)&out[(size_t)(r+8)*256 + c] = make_float2(acc[0][nt][2], acc[0][nt][3]);
    }
}

// ---------------- host launcher ----------------
extern "C" void kernel_launch(void* const* d_in, const int* in_sizes, int n_in,
                              void* d_out, int out_size)
{
    const float *t, *slots, *kin, *vin;
    const float *w0[4], *b0[4], *w1[4], *b1[4], *wp[4], *bp[4];
    const float *lnAw, *lnAb, *lnFw, *lnFb;

    if (in_sizes[0] == 1) {
        t     = (const float*)d_in[0];
        slots = (const float*)d_in[1];
        kin   = (const float*)d_in[2];
        vin   = (const float*)d_in[3];
        for (int h = 0; h < 4; h++) {
            int base = 4 + h*6;
            w0[h] = (const float*)d_in[base+0];  b0[h] = (const float*)d_in[base+1];
            w1[h] = (const float*)d_in[base+2];  b1[h] = (const float*)d_in[base+3];
            wp[h] = (const float*)d_in[base+4];  bp[h] = (const float*)d_in[base+5];
        }
        lnAw = (const float*)d_in[28]; lnAb = (const float*)d_in[29];
        lnFw = (const float*)d_in[30]; lnFb = (const float*)d_in[31];
    } else {
        for (int h = 0; h < 4; h++) {
            int base = h*6;
            w0[h] = (const float*)d_in[base+0];  b0[h] = (const float*)d_in[base+1];
            w1[h] = (const float*)d_in[base+2];  b1[h] = (const float*)d_in[base+3];
            wp[h] = (const float*)d_in[base+4];  bp[h] = (const float*)d_in[base+5];
        }
        lnAw = (const float*)d_in[24]; lnAb = (const float*)d_in[25];
        lnFw = (const float*)d_in[26]; lnFb = (const float*)d_in[27];
        t     = (const float*)d_in[28];
        slots = (const float*)d_in[29];
        kin   = (const float*)d_in[30];
        vin   = (const float*)d_in[31];
    }

    tdw_kernel<<<4, 128>>>(t,
        w0[0],b0[0],w1[0],b1[0],  w0[1],b0[1],w1[1],b1[1],
        w0[2],b0[2],w1[2],b1[2],  w0[3],b0[3],w1[3],b1[3]);

    wmat_kernel<<<30720, 256>>>(wp[0],bp[0], wp[1],bp[1], wp[2],bp[2], wp[3],bp[3]);

    ln_kernel<<<(B_*NS)/8, 256>>>(slots, lnAw, lnAb, lnFw, lnFb);

    const int SMEM_64  = 2*(64*36 + 128*36)*4;     // 55296
    const int SMEM_128 = 2*(128*36 + 128*36)*4;    // 73728
    const int SMEM_AV  = (2*128*36 + 2*32*168)*4;  // 79872

    cudaFuncSetAttribute(gemm_q_tf32,   cudaFuncAttributeMaxDynamicSharedMemorySize, SMEM_64);
    gemm_q_tf32<<<dim3(64, 2), 256, SMEM_64>>>();

    cudaFuncSetAttribute(attn_qk_kernel, cudaFuncAttributeMaxDynamicSharedMemorySize, SMEM_128);
    attn_qk_kernel<<<dim3(B_, NMT), 256, SMEM_128>>>(kin);

    rowinv_kernel<<<B_, 128>>>();

    cudaFuncSetAttribute(attn_av_kernel, cudaFuncAttributeMaxDynamicSharedMemorySize, SMEM_AV);
    attn_av_kernel<<<dim3(B_, 2, 4), 256, SMEM_AV>>>(vin);

    av_combine_kernel<<<(B_*NS*SD/4)/256, 256>>>();

    cudaFuncSetAttribute(gemm_ff0_tf32, cudaFuncAttributeMaxDynamicSharedMemorySize, SMEM_128);
    gemm_ff0_tf32<<<dim3(32, 8), 256, SMEM_128>>>();

    cudaFuncSetAttribute(gemm_out_tf32, cudaFuncAttributeMaxDynamicSharedMemorySize, SMEM_64);
    gemm_out_tf32<<<dim3(64, 2), 256, SMEM_64>>>((float*)d_out);
}

// round 6
// speedup vs baseline: 4.4343x; 1.4620x over previous
#include <cuda_runtime.h>
#include <cuda_fp16.h>

#define B_    32
#define NS    128
#define SD    256
#define NF    4096
#define MH    1024
#define NMT   32

// ---------------- device scratch ----------------
__device__ float g_h[4][64];
__device__ __align__(16) __half g_Wq_h [SD*SD];
__device__ __align__(16) __half g_Wg_h [SD*2*SD];
__device__ __align__(16) __half g_Wf0_h[MH*2*SD];
__device__ __align__(16) __half g_Wf1_h[SD*MH];
__device__ __align__(16) __half g_snA_h[B_*NS*SD];
__device__ __align__(16) __half g_snF_h[B_*NS*SD];
__device__ __align__(16) __half g_q_h  [B_*NS*SD];
__device__ __align__(16) __half g_att_h[(size_t)B_*NS*NF];
__device__ __align__(16) __half g_fattn_h[B_*NS*SD];
__device__ __align__(16) __half g_Hbuf_h[B_*NS*MH];
__device__ float g_srow[B_*NMT*NS];
__device__ float g_rowinv[B_*NS];
__device__ float g_avp[(size_t)4*B_*NS*SD];
__device__ __align__(16) float g_fattn[B_*NS*SD];

// ---------------- helpers ----------------
#define CP_COMMIT asm volatile("cp.async.commit_group;\n" ::: "memory")
#define CP_WAIT0  asm volatile("cp.async.wait_group 0;\n" ::: "memory")
__device__ __forceinline__ void cpa16(unsigned d, const void* s) {
    asm volatile("cp.async.ca.shared.global [%0], [%1], 16;\n" :: "r"(d), "l"(s));
}
__device__ __forceinline__ void mma16(float c[4], const unsigned a[4], const unsigned b[2]) {
    asm volatile("mma.sync.aligned.m16n8k16.row.col.f32.f16.f16.f32 "
        "{%0,%1,%2,%3},{%4,%5,%6,%7},{%8,%9},{%0,%1,%2,%3};"
        : "+f"(c[0]), "+f"(c[1]), "+f"(c[2]), "+f"(c[3])
        : "r"(a[0]), "r"(a[1]), "r"(a[2]), "r"(a[3]), "r"(b[0]), "r"(b[1]));
}
__device__ __forceinline__ void ldsm4(unsigned r[4], unsigned addr) {
    asm volatile("ldmatrix.sync.aligned.m8n8.x4.shared.b16 {%0,%1,%2,%3}, [%4];"
        : "=r"(r[0]), "=r"(r[1]), "=r"(r[2]), "=r"(r[3]) : "r"(addr));
}
__device__ __forceinline__ void ldsm4t(unsigned r[4], unsigned addr) {
    asm volatile("ldmatrix.sync.aligned.m8n8.x4.trans.shared.b16 {%0,%1,%2,%3}, [%4];"
        : "=r"(r[0]), "=r"(r[1]), "=r"(r[2]), "=r"(r[3]) : "r"(addr));
}
__device__ __forceinline__ uint4 pack8(const float4& a, const float4& b) {
    __half2 h0 = __floats2half2_rn(a.x, a.y), h1 = __floats2half2_rn(a.z, a.w);
    __half2 h2 = __floats2half2_rn(b.x, b.y), h3 = __floats2half2_rn(b.z, b.w);
    uint4 u;
    u.x = *(unsigned*)&h0; u.y = *(unsigned*)&h1;
    u.z = *(unsigned*)&h2; u.w = *(unsigned*)&h3;
    return u;
}

// ---- cp.async of a BM x 32-half tile, smem row stride 80 B ----
template<int BM>
__device__ __forceinline__ void cpa_tile16(unsigned sb, const __half* a0, int lda0,
                                           const __half* a1, int lda1, int split,
                                           int k0, int tid)
{
    if (BM == 128) {
        int r = tid >> 1, s = tid & 1;
        #pragma unroll
        for (int j = 0; j < 2; j++) {
            int k = k0 + s*16 + j*8;
            const __half* src = (k < split) ? a0 + (size_t)r*lda0 + k
                                            : a1 + (size_t)r*lda1 + (k - split);
            cpa16(sb + (unsigned)(r*80 + s*32 + j*16), src);
        }
    } else {   // BM == 64
        int r = tid >> 2, s = tid & 3;
        int k = k0 + s*8;
        const __half* src = (k < split) ? a0 + (size_t)r*lda0 + k
                                        : a1 + (size_t)r*lda1 + (k - split);
        cpa16(sb + (unsigned)(r*80 + s*16), src);
    }
}

// ---- inner compute: BK=32 chunk, A/B in [rows][32k] 80B-stride ----
template<int MT>
__device__ __forceinline__ void comp16(unsigned Ab, unsigned Bb,
                                       float acc[][8][4], int wr, int wc, int lane)
{
    int quad = lane >> 3, l7 = lane & 7;
    #pragma unroll
    for (int s = 0; s < 2; s++) {
        unsigned a[MT][4];
        #pragma unroll
        for (int mt = 0; mt < MT; mt++)
            ldsm4(a[mt], Ab + (unsigned)((wr + mt*16 + (quad&1)*8 + l7)*80 + s*32 + (quad>>1)*16));
        #pragma unroll
        for (int nt16 = 0; nt16 < 4; nt16++) {
            unsigned bm4[4];
            ldsm4(bm4, Bb + (unsigned)((wc + nt16*16 + (quad>>1)*8 + l7)*80 + s*32 + (quad&1)*16));
            #pragma unroll
            for (int oct = 0; oct < 2; oct++)
                #pragma unroll
                for (int mt = 0; mt < MT; mt++)
                    mma16(acc[mt][nt16*2+oct], a[mt], &bm4[oct*2]);
        }
    }
}
// ---- inner compute with B stored [k][n] 272B-stride (V tile), trans ldmatrix ----
__device__ __forceinline__ void comp16_vt(unsigned Ab, unsigned Bb,
                                          float acc[][8][4], int wr, int wc, int lane)
{
    int quad = lane >> 3, l7 = lane & 7;
    #pragma unroll
    for (int s = 0; s < 2; s++) {
        unsigned a[2][4];
        #pragma unroll
        for (int mt = 0; mt < 2; mt++)
            ldsm4(a[mt], Ab + (unsigned)((wr + mt*16 + (quad&1)*8 + l7)*80 + s*32 + (quad>>1)*16));
        #pragma unroll
        for (int nt16 = 0; nt16 < 4; nt16++) {
            unsigned bm4[4];
            ldsm4t(bm4, Bb + (unsigned)((s*16 + (quad&1)*8 + l7)*272 + (wc + nt16*16 + (quad>>1)*8)*2));
            #pragma unroll
            for (int oct = 0; oct < 2; oct++)
                #pragma unroll
                for (int mt = 0; mt < 2; mt++)
                    mma16(acc[mt][nt16*2+oct], a[mt], &bm4[oct*2]);
        }
    }
}

// ---- double-buffered all-cp.async fp16 GEMM ----
template<int MT>
__device__ __forceinline__ void h_gemm_async(unsigned sbase,
    const __half* a0, int lda0, const __half* a1, int lda1, int split,
    const __half* b, int ldb, int nchunks,
    float acc[][8][4], int wr, int wc, int lane, int tid)
{
    const unsigned ABUF = MT*64*80;
    unsigned aoff[2] = {sbase, sbase + ABUF};
    unsigned boff[2] = {sbase + 2*ABUF, sbase + 2*ABUF + 128*80};
    cpa_tile16<MT*64>(aoff[0], a0, lda0, a1, lda1, split, 0, tid);
    cpa_tile16<128>(boff[0], b, ldb, b, ldb, 1<<30, 0, tid);
    CP_COMMIT;
    for (int c = 0; c < nchunks; c++) {
        CP_WAIT0; __syncthreads();
        if (c + 1 < nchunks) {
            cpa_tile16<MT*64>(aoff[(c+1)&1], a0, lda0, a1, lda1, split, (c+1)*32, tid);
            cpa_tile16<128>(boff[(c+1)&1], b, ldb, b, ldb, 1<<30, (c+1)*32, tid);
            CP_COMMIT;
        }
        comp16<MT>(aoff[c&1], boff[c&1], acc, wr, wc, lane);
        __syncthreads();
    }
}

// ---- staged fp32->fp16 loaders ----
__device__ __forceinline__ void ldgK(float4 p[4], const float* Kb, int k0, int tid) {
    int n = tid >> 1, c0 = (tid & 1) * 16;
    const float* s = Kb + (size_t)n*256 + k0 + c0;
    #pragma unroll
    for (int j = 0; j < 4; j++) p[j] = ((const float4*)s)[j];
}
__device__ __forceinline__ void stsK(unsigned char* buf, const float4 p[4], int tid) {
    int n = tid >> 1, c0 = tid & 1;
    *(uint4*)(buf + n*80 + c0*32)      = pack8(p[0], p[1]);
    *(uint4*)(buf + n*80 + c0*32 + 16) = pack8(p[2], p[3]);
}
__device__ __forceinline__ void ldgV(float4 p[4], const float* Vb, int m0, int tid) {
    int k = tid >> 3, n0 = (tid & 7) * 16;
    const float* s = Vb + (size_t)(m0 + k)*256 + n0;
    #pragma unroll
    for (int j = 0; j < 4; j++) p[j] = ((const float4*)s)[j];
}
__device__ __forceinline__ void stsV(unsigned char* buf, const float4 p[4], int tid) {
    int k = tid >> 3, n0 = (tid & 7) * 16;
    *(uint4*)(buf + k*272 + n0*2)      = pack8(p[0], p[1]);
    *(uint4*)(buf + k*272 + n0*2 + 16) = pack8(p[2], p[3]);
}

// ---------------- 1) time MLP heads ----------------
__global__ void tdw_kernel(const float* t,
    const float* qw0,const float* qb0,const float* qw1,const float* qb1,
    const float* gw0,const float* gb0,const float* gw1,const float* gb1,
    const float* f0w0,const float* f0b0,const float* f0w1,const float* f0b1,
    const float* f1w0,const float* f1b0,const float* f1w1,const float* f1b1)
{
    __shared__ float emb[257];
    __shared__ float h0[64];
    const float* w0s[4] = {qw0,gw0,f0w0,f1w0};
    const float* b0s[4] = {qb0,gb0,f0b0,f1b0};
    const float* w1s[4] = {qw1,gw1,f0w1,f1w1};
    const float* b1s[4] = {qb1,gb1,f0b1,f1b1};
    int head = blockIdx.x, tid = threadIdx.x;
    float tv = t[0];
    const float C = -9.210340371976184f / 128.0f;
    for (int j = tid; j < 257; j += blockDim.x) {
        float e;
        if (j == 0)        e = tv;
        else if (j <= 128) e = sinf(C * (float)(j-1)   * tv);
        else               e = cosf(C * (float)(j-129) * tv);
        emb[j] = e;
    }
    __syncthreads();
    int warp = tid >> 5, lane = tid & 31;
    const float* w0 = w0s[head];
    for (int r = warp; r < 64; r += 4) {
        float s = 0.f;
        for (int j = lane; j < 257; j += 32) s += w0[r*257 + j] * emb[j];
        #pragma unroll
        for (int o = 16; o; o >>= 1) s += __shfl_xor_sync(0xffffffffu, s, o);
        if (lane == 0) { s += b0s[head][r]; h0[r] = s / (1.f + expf(-s)); }
    }
    __syncthreads();
    if (tid < 64) {
        const float* w1 = w1s[head];
        float s = 0.f;
        #pragma unroll 8
        for (int j = 0; j < 64; j++) s += w1[tid*64 + j] * h0[j];
        s += b1s[head][tid];
        g_h[head][tid] = s / (1.f + expf(-s));
    }
}

// ---------------- 2) materialize W (fp16), 8 rows/warp ----------------
__global__ void wmat_kernel(const float* __restrict__ wp_q,  const float* __restrict__ bp_q,
                            const float* __restrict__ wp_g,  const float* __restrict__ bp_g,
                            const float* __restrict__ wp_f0, const float* __restrict__ bp_f0,
                            const float* __restrict__ wp_f1, const float* __restrict__ bp_f1)
{
    int gwarp = (blockIdx.x * 256 + threadIdx.x) >> 5;
    int lane  = threadIdx.x & 31;
    int rl = lane >> 2, sub = lane & 3;
    int r8 = gwarp * 8 + rl;
    const float* wp; const float* bp; __half* W; int r; int which;
    if (r8 < 65536)       { wp = wp_q;  bp = bp_q;  W = g_Wq_h;  r = r8;          which = 0; }
    else if (r8 < 196608) { wp = wp_g;  bp = bp_g;  W = g_Wg_h;  r = r8 - 65536;  which = 1; }
    else if (r8 < 720896) { wp = wp_f0; bp = bp_f0; W = g_Wf0_h; r = r8 - 196608; which = 2; }
    else                  { wp = wp_f1; bp = bp_f1; W = g_Wf1_h; r = r8 - 720896; which = 3; }
    const float* hv = g_h[which];
    float p = 0.f;
    #pragma unroll
    for (int j = 0; j < 4; j++) {
        float4 w  = *(const float4*)&wp[(size_t)r*64 + sub*16 + 4*j];
        float4 hh = *(const float4*)&hv[sub*16 + 4*j];
        p += w.x*hh.x + w.y*hh.y + w.z*hh.z + w.w*hh.w;
    }
    p += __shfl_down_sync(0xffffffffu, p, 2);
    p += __shfl_down_sync(0xffffffffu, p, 1);
    if (sub == 0) W[r] = __float2half_rn(p + bp[r]);
}

// ---------------- 3) dual LayerNorm (fp16 out) ----------------
__global__ void ln_kernel(const float* __restrict__ slots,
                          const float* __restrict__ aw, const float* __restrict__ ab,
                          const float* __restrict__ fw, const float* __restrict__ fb)
{
    int warp = threadIdx.x >> 5, lane = threadIdx.x & 31;
    int row  = blockIdx.x * 8 + warp;
    const float* x = slots + (size_t)row * 256;
    float4 x0 = *(const float4*)&x[lane*4];
    float4 x1 = *(const float4*)&x[128 + lane*4];
    float s = x0.x+x0.y+x0.z+x0.w + x1.x+x1.y+x1.z+x1.w;
    #pragma unroll
    for (int o = 16; o; o >>= 1) s += __shfl_xor_sync(0xffffffffu, s, o);
    float mu = s * (1.f/256.f);
    float d, q = 0.f;
    d = x0.x-mu; q += d*d;  d = x0.y-mu; q += d*d;
    d = x0.z-mu; q += d*d;  d = x0.w-mu; q += d*d;
    d = x1.x-mu; q += d*d;  d = x1.y-mu; q += d*d;
    d = x1.z-mu; q += d*d;  d = x1.w-mu; q += d*d;
    #pragma unroll
    for (int o = 16; o; o >>= 1) q += __shfl_xor_sync(0xffffffffu, q, o);
    float rstd = rsqrtf(q * (1.f/256.f) + 1e-5f);

    float4 aw0 = *(const float4*)&aw[lane*4],  aw1 = *(const float4*)&aw[128+lane*4];
    float4 ab0 = *(const float4*)&ab[lane*4],  ab1 = *(const float4*)&ab[128+lane*4];
    float4 fw0 = *(const float4*)&fw[lane*4],  fw1 = *(const float4*)&fw[128+lane*4];
    float4 fb0 = *(const float4*)&fb[lane*4],  fb1 = *(const float4*)&fb[128+lane*4];

    float4 yA0, yA1, yF0, yF1;
    yA0.x = (x0.x-mu)*rstd*aw0.x + ab0.x;  yA0.y = (x0.y-mu)*rstd*aw0.y + ab0.y;
    yA0.z = (x0.z-mu)*rstd*aw0.z + ab0.z;  yA0.w = (x0.w-mu)*rstd*aw0.w + ab0.w;
    yA1.x = (x1.x-mu)*rstd*aw1.x + ab1.x;  yA1.y = (x1.y-mu)*rstd*aw1.y + ab1.y;
    yA1.z = (x1.z-mu)*rstd*aw1.z + ab1.z;  yA1.w = (x1.w-mu)*rstd*aw1.w + ab1.w;
    yF0.x = (x0.x-mu)*rstd*fw0.x + fb0.x;  yF0.y = (x0.y-mu)*rstd*fw0.y + fb0.y;
    yF0.z = (x0.z-mu)*rstd*fw0.z + fb0.z;  yF0.w = (x0.w-mu)*rstd*fw0.w + fb0.w;
    yF1.x = (x1.x-mu)*rstd*fw1.x + fb1.x;  yF1.y = (x1.y-mu)*rstd*fw1.y + fb1.y;
    yF1.z = (x1.z-mu)*rstd*fw1.z + fb1.z;  yF1.w = (x1.w-mu)*rstd*fw1.w + fb1.w;

    *(uint4*)&g_snA_h[(size_t)row*256 + lane*8]  = pack8(yA0, *(float4*)&g_snA_h); // placeholder overwritten below
    // NOTE: write both halves properly:
    *(uint2*)&g_snA_h[(size_t)row*256 + lane*4] = make_uint2(
        __half2_raw(__floats2half2_rn(yA0.x, yA0.y)).x ? 0u : 0u, 0u);
}

// The ln kernel above got unwieldy — define a clean version and use it instead.
__global__ void ln_kernel2(const float* __restrict__ slots,
                           const float* __restrict__ aw, const float* __restrict__ ab,
                           const float* __restrict__ fw, const float* __restrict__ fb)
{
    int warp = threadIdx.x >> 5, lane = threadIdx.x & 31;
    int row  = blockIdx.x * 8 + warp;
    const float* x = slots + (size_t)row * 256;
    float v[8];
    *(float4*)&v[0] = *(const float4*)&x[lane*4];
    *(float4*)&v[4] = *(const float4*)&x[128 + lane*4];
    float s = 0.f;
    #pragma unroll
    for (int i = 0; i < 8; i++) s += v[i];
    #pragma unroll
    for (int o = 16; o; o >>= 1) s += __shfl_xor_sync(0xffffffffu, s, o);
    float mu = s * (1.f/256.f);
    float q = 0.f;
    #pragma unroll
    for (int i = 0; i < 8; i++) { float d = v[i]-mu; q += d*d; }
    #pragma unroll
    for (int o = 16; o; o >>= 1) q += __shfl_xor_sync(0xffffffffu, q, o);
    float rstd = rsqrtf(q * (1.f/256.f) + 1e-5f);
    float A[8], F[8];
    #pragma unroll
    for (int h = 0; h < 2; h++) {
        int base = h ? 128 + lane*4 : lane*4;
        float4 awv = *(const float4*)&aw[base], abv = *(const float4*)&ab[base];
        float4 fwv = *(const float4*)&fw[base], fbv = *(const float4*)&fb[base];
        const float* vv = &v[h*4];
        float* Av = &A[h*4]; float* Fv = &F[h*4];
        Av[0]=(vv[0]-mu)*rstd*awv.x+abv.x; Av[1]=(vv[1]-mu)*rstd*awv.y+abv.y;
        Av[2]=(vv[2]-mu)*rstd*awv.z+abv.z; Av[3]=(vv[3]-mu)*rstd*awv.w+abv.w;
        Fv[0]=(vv[0]-mu)*rstd*fwv.x+fbv.x; Fv[1]=(vv[1]-mu)*rstd*fwv.y+fbv.y;
        Fv[2]=(vv[2]-mu)*rstd*fwv.z+fbv.z; Fv[3]=(vv[3]-mu)*rstd*fwv.w+fbv.w;
        *(uint2*)&g_snA_h[(size_t)row*256 + base] = make_uint2(
            *(unsigned*)&(__half2&)*(__half2[]){__floats2half2_rn(Av[0],Av[1])},
            *(unsigned*)&(__half2&)*(__half2[]){__floats2half2_rn(Av[2],Av[3])});
        *(uint2*)&g_snF_h[(size_t)row*256 + base] = make_uint2(
            *(unsigned*)&(__half2&)*(__half2[]){__floats2half2_rn(Fv[0],Fv[1])},
            *(unsigned*)&(__half2&)*(__half2[]){__floats2half2_rn(Fv[2],Fv[3])});
    }
}

// ---------------- 4) q = snA @ Wq^T ----------------
__global__ __launch_bounds__(256) void gemm_q_h()
{
    extern __shared__ unsigned char smp[];
    unsigned sbase = (unsigned)__cvta_generic_to_shared(smp);
    int tid = threadIdx.x, lane = tid & 31;
    int g = lane >> 2, t = lane & 3;
    int wid = tid >> 5, wr = (wid >> 1) * 16, wc = (wid & 1) * 64;
    int bm = blockIdx.x * 64, bn = blockIdx.y * 128;
    float acc[1][8][4] = {};
    h_gemm_async<1>(sbase, g_snA_h + (size_t)bm*256, 256, g_snA_h, 256, 1<<30,
                    g_Wq_h + (size_t)bn*256, 256, 8, acc, wr, wc, lane, tid);
    #pragma unroll
    for (int nt = 0; nt < 8; nt++) {
        int r = bm + wr + g, c = bn + wc + nt*8 + 2*t;
        __half2 h0 = __floats2half2_rn(acc[0][nt][0], acc[0][nt][1]);
        __half2 h1 = __floats2half2_rn(acc[0][nt][2], acc[0][nt][3]);
        *(__half2*)&g_q_h[(size_t)r*256 + c]     = h0;
        *(__half2*)&g_q_h[(size_t)(r+8)*256 + c] = h1;
    }
}

// ---------------- 5) QK^T + tile-local softmax -> fp16 att probs ----------------
__global__ __launch_bounds__(256) void attn_qk_kernel(const float* __restrict__ Kin)
{
    extern __shared__ unsigned char smp[];
    unsigned sbase = (unsigned)__cvta_generic_to_shared(smp);
    unsigned aoff[2] = {sbase, sbase + 10240};
    unsigned boff[2] = {sbase + 20480, sbase + 30720};
    float* L = (float*)(smp + 40960);      // [128][132]
    int b = blockIdx.x, mt_ = blockIdx.y;
    int tid = threadIdx.x, lane = tid & 31;
    int g = lane >> 2, t = lane & 3;
    int wid = tid >> 5, wr = (wid >> 1) * 32, wc = (wid & 1) * 64;
    const __half* Q = g_q_h + (size_t)b*128*256;
    const float* Kb = Kin + ((size_t)b*NF + mt_*128)*256;
    float acc[2][8][4] = {};
    cpa_tile16<128>(aoff[0], Q, 256, Q, 256, 1<<30, 0, tid);
    CP_COMMIT;
    float4 pb[4];
    ldgK(pb, Kb, 0, tid);
    for (int c = 0; c < 8; c++) {
        stsK(smp + 20480 + (c&1)*10240, pb, tid);
        CP_WAIT0; __syncthreads();
        if (c + 1 < 8) {
            cpa_tile16<128>(aoff[(c+1)&1], Q, 256, Q, 256, 1<<30, (c+1)*32, tid);
            CP_COMMIT;
            ldgK(pb, Kb, (c+1)*32, tid);
        }
        comp16<2>(aoff[c&1], boff[c&1], acc, wr, wc, lane);
        __syncthreads();
    }
    const float scale = 0.0625f;
    #pragma unroll
    for (int mt = 0; mt < 2; mt++)
        #pragma unroll
        for (int nt = 0; nt < 8; nt++) {
            int r = wr + mt*16 + g, c = wc + nt*8 + 2*t;
            L[r*132 + c]       = acc[mt][nt][0]*scale;
            L[r*132 + c + 1]   = acc[mt][nt][1]*scale;
            L[(r+8)*132 + c]   = acc[mt][nt][2]*scale;
            L[(r+8)*132 + c+1] = acc[mt][nt][3]*scale;
        }
    __syncthreads();
    if (tid < 128) {
        int m = tid;
        float mx = -1e30f;
        #pragma unroll 4
        for (int n = 0; n < 128; n++) mx = fmaxf(mx, L[n*132 + m]);
        float s = 0.f;
        #pragma unroll 4
        for (int n = 0; n < 128; n++) {
            float e = __expf(L[n*132 + m] - mx);
            L[n*132 + m] = e;  s += e;
        }
        float inv = 1.f / s;
        #pragma unroll 4
        for (int n = 0; n < 128; n++) L[n*132 + m] *= inv;
    }
    __syncthreads();
    if (tid < 128) {
        int n = tid; float rs = 0.f;
        #pragma unroll 4
        for (int m = 0; m < 128; m++) rs += L[n*132 + m];
        g_srow[(b*NMT + mt_)*128 + n] = rs;
    }
    int n = tid >> 1, mh = (tid & 1) * 64;
    __half* dst = g_att_h + ((size_t)b*128 + n)*NF + mt_*128 + mh;
    #pragma unroll
    for (int j = 0; j < 8; j++) {
        float4 v0 = *(float4*)&L[n*132 + mh + 8*j];
        float4 v1 = *(float4*)&L[n*132 + mh + 8*j + 4];
        *(uint4*)(dst + 8*j) = pack8(v0, v1);
    }
}

// ---------------- 6) row-sum reduce -> 1/(s+eps) ----------------
__global__ void rowinv_kernel()
{
    int b = blockIdx.x, n = threadIdx.x;
    float s = 0.f;
    #pragma unroll 8
    for (int mt = 0; mt < NMT; mt++) s += g_srow[(b*NMT + mt)*128 + n];
    g_rowinv[b*128 + n] = 1.f / (s + 1e-8f);
}

// ---------------- 7) att @ V (split-K=4) ----------------
__global__ __launch_bounds__(256) void attn_av_kernel(const float* __restrict__ Vin)
{
    extern __shared__ unsigned char smp[];
    unsigned sbase = (unsigned)__cvta_generic_to_shared(smp);
    unsigned aoff[2] = {sbase, sbase + 10240};
    unsigned boff[2] = {sbase + 20480, sbase + 20480 + 8704};
    int b = blockIdx.x, dt = blockIdx.y, ks_ = blockIdx.z;
    int tid = threadIdx.x, lane = tid & 31;
    int g = lane >> 2, t = lane & 3;
    int wid = tid >> 5, wr = (wid >> 1) * 32, wc = (wid & 1) * 64;
    const __half* Ap = g_att_h + (size_t)b*128*NF + ks_*1024;
    const float* Bv = Vin + ((size_t)b*NF + ks_*1024)*256 + dt*128;
    float acc[2][8][4] = {};
    cpa_tile16<128>(aoff[0], Ap, NF, Ap, NF, 1<<30, 0, tid);
    CP_COMMIT;
    float4 pv[4];
    ldgV(pv, Bv, 0, tid);
    for (int c = 0; c < 32; c++) {
        stsV(smp + 20480 + (c&1)*8704, pv, tid);
        CP_WAIT0; __syncthreads();
        if (c + 1 < 32) {
            cpa_tile16<128>(aoff[(c+1)&1], Ap, NF, Ap, NF, 1<<30, (c+1)*32, tid);
            CP_COMMIT;
            ldgV(pv, Bv, (c+1)*32, tid);
        }
        comp16_vt(aoff[c&1], boff[c&1], acc, wr, wc, lane);
        __syncthreads();
    }
    float* P = g_avp + ((size_t)ks_*B_ + b)*128*256 + dt*128;
    #pragma unroll
    for (int mt = 0; mt < 2; mt++)
        #pragma unroll
        for (int nt = 0; nt < 8; nt++) {
            int r = wr + mt*16 + g, c = wc + nt*8 + 2*t;
            *(float2*)&P[(size_t)r*256 + c]     = make_float2(acc[mt][nt][0], acc[mt][nt][1]);
            *(float2*)&P[(size_t)(r+8)*256 + c] = make_float2(acc[mt][nt][2], acc[mt][nt][3]);
        }
}

// ---------------- 8) combine split-K + renorm ----------------
__global__ void av_combine_kernel()
{
    int idx = blockIdx.x * 256 + threadIdx.x;
    int row = idx >> 6;
    float inv = g_rowinv[row];
    const size_t STR = (size_t)B_*NS*SD;
    float4 p0 = *(float4*)&g_avp[(size_t)idx*4];
    float4 p1 = *(float4*)&g_avp[STR   + (size_t)idx*4];
    float4 p2 = *(float4*)&g_avp[2*STR + (size_t)idx*4];
    float4 p3 = *(float4*)&g_avp[3*STR + (size_t)idx*4];
    float4 o;
    o.x = (p0.x + p1.x + p2.x + p3.x) * inv;
    o.y = (p0.y + p1.y + p2.y + p3.y) * inv;
    o.z = (p0.z + p1.z + p2.z + p3.z) * inv;
    o.w = (p0.w + p1.w + p2.w + p3.w) * inv;
    *(float4*)&g_fattn[(size_t)idx*4] = o;
    __half2 h0 = __floats2half2_rn(o.x, o.y), h1 = __floats2half2_rn(o.z, o.w);
    uint2 u = {*(unsigned*)&h0, *(unsigned*)&h1};
    *(uint2*)&g_fattn_h[(size_t)idx*4] = u;
}

// ---------------- 9) H = relu([snF|fattn] @ Wf0^T) ----------------
__global__ __launch_bounds__(256) void gemm_ff0_h()
{
    extern __shared__ unsigned char smp[];
    unsigned sbase = (unsigned)__cvta_generic_to_shared(smp);
    int tid = threadIdx.x, lane = tid & 31;
    int g = lane >> 2, t = lane & 3;
    int wid = tid >> 5, wr = (wid >> 1) * 32, wc = (wid & 1) * 64;
    int bm = blockIdx.x * 128, bn = blockIdx.y * 128;
    float acc[2][8][4] = {};
    h_gemm_async<2>(sbase, g_snF_h + (size_t)bm*256, 256, g_fattn_h + (size_t)bm*256, 256, 256,
                    g_Wf0_h + (size_t)bn*512, 512, 16, acc, wr, wc, lane, tid);
    #pragma unroll
    for (int mt = 0; mt < 2; mt++)
        #pragma unroll
        for (int nt = 0; nt < 8; nt++) {
            int r = bm + wr + mt*16 + g, c = bn + wc + nt*8 + 2*t;
            __half2 h0 = __floats2half2_rn(fmaxf(acc[mt][nt][0],0.f), fmaxf(acc[mt][nt][1],0.f));
            __half2 h1 = __floats2half2_rn(fmaxf(acc[mt][nt][2],0.f), fmaxf(acc[mt][nt][3],0.f));
            *(__half2*)&g_Hbuf_h[(size_t)r*1024 + c]     = h0;
            *(__half2*)&g_Hbuf_h[(size_t)(r+8)*1024 + c] = h1;
        }
}

// ---------------- 10) out = sigmoid([snA|fattn]@Wg^T)*fattn + H@Wf1^T ----------------
__global__ __launch_bounds__(256) void gemm_out_h(float* __restrict__ out)
{
    extern __shared__ unsigned char smp[];
    unsigned sbase = (unsigned)__cvta_generic_to_shared(smp);
    int tid = threadIdx.x, lane = tid & 31;
    int g = lane >> 2, t = lane & 3;
    int wid = tid >> 5, wr = (wid >> 1) * 16, wc = (wid & 1) * 64;
    int bm = blockIdx.x * 64, bn = blockIdx.y * 128;
    float acc[1][8][4] = {};
    h_gemm_async<1>(sbase, g_snA_h + (size_t)bm*256, 256, g_fattn_h + (size_t)bm*256, 256, 256,
                    g_Wg_h + (size_t)bn*512, 512, 16, acc, wr, wc, lane, tid);
    #pragma unroll
    for (int nt = 0; nt < 8; nt++) {
        int r = bm + wr + g, c = bn + wc + nt*8 + 2*t;
        float2 f0 = *(const float2*)&g_fattn[(size_t)r*256 + c];
        float2 f1 = *(const float2*)&g_fattn[(size_t)(r+8)*256 + c];
        acc[0][nt][0] = f0.x / (1.f + __expf(-acc[0][nt][0]));
        acc[0][nt][1] = f0.y / (1.f + __expf(-acc[0][nt][1]));
        acc[0][nt][2] = f1.x / (1.f + __expf(-acc[0][nt][2]));
        acc[0][nt][3] = f1.y / (1.f + __expf(-acc[0][nt][3]));
    }
    h_gemm_async<1>(sbase, g_Hbuf_h + (size_t)bm*1024, 1024, g_Hbuf_h, 1024, 1<<30,
                    g_Wf1_h + (size_t)bn*1024, 1024, 32, acc, wr, wc, lane, tid);
    #pragma unroll
    for (int nt = 0; nt < 8; nt++) {
        int r = bm + wr + g, c = bn + wc + nt*8 + 2*t;
        *(float2*)&out[(size_t)r*256 + c]     = make_float2(acc[0][nt][0], acc[0][nt][1]);
        *(float2*)&out[(size_t)(r+8)*256 + c] = make_float2(acc[0][nt][2], acc[0][nt][3]);
    }
}

// ---------------- host launcher ----------------
extern "C" void kernel_launch(void* const* d_in, const int* in_sizes, int n_in,
                              void* d_out, int out_size)
{
    const float *t, *slots, *kin, *vin;
    const float *w0[4], *b0[4], *w1[4], *b1[4], *wp[4], *bp[4];
    const float *lnAw, *lnAb, *lnFw, *lnFb;

    if (in_sizes[0] == 1) {
        t     = (const float*)d_in[0];
        slots = (const float*)d_in[1];
        kin   = (const float*)d_in[2];
        vin   = (const float*)d_in[3];
        for (int h = 0; h < 4; h++) {
            int base = 4 + h*6;
            w0[h] = (const float*)d_in[base+0];  b0[h] = (const float*)d_in[base+1];
            w1[h] = (const float*)d_in[base+2];  b1[h] = (const float*)d_in[base+3];
            wp[h] = (const float*)d_in[base+4];  bp[h] = (const float*)d_in[base+5];
        }
        lnAw = (const float*)d_in[28]; lnAb = (const float*)d_in[29];
        lnFw = (const float*)d_in[30]; lnFb = (const float*)d_in[31];
    } else {
        for (int h = 0; h < 4; h++) {
            int base = h*6;
            w0[h] = (const float*)d_in[base+0];  b0[h] = (const float*)d_in[base+1];
            w1[h] = (const float*)d_in[base+2];  b1[h] = (const float*)d_in[base+3];
            wp[h] = (const float*)d_in[base+4];  bp[h] = (const float*)d_in[base+5];
        }
        lnAw = (const float*)d_in[24]; lnAb = (const float*)d_in[25];
        lnFw = (const float*)d_in[26]; lnFb = (const float*)d_in[27];
        t     = (const float*)d_in[28];
        slots = (const float*)d_in[29];
        kin   = (const float*)d_in[30];
        vin   = (const float*)d_in[31];
    }

    tdw_kernel<<<4, 128>>>(t,
        w0[0],b0[0],w1[0],b1[0],  w0[1],b0[1],w1[1],b1[1],
        w0[2],b0[2],w1[2],b1[2],  w0[3],b0[3],w1[3],b1[3]);

    wmat_kernel<<<15360, 256>>>(wp[0],bp[0], wp[1],bp[1], wp[2],bp[2], wp[3],bp[3]);

    ln_kernel2<<<(B_*NS)/8, 256>>>(slots, lnAw, lnAb, lnFw, lnFb);

    const int SMEM_Q   = 30720;
    const int SMEM_QK  = 40960 + 128*132*4;   // 108544
    const int SMEM_AV  = 20480 + 2*8704;      // 37888
    const int SMEM_FF0 = 40960;
    const int SMEM_OUT = 30720;

    cudaFuncSetAttribute(gemm_q_h, cudaFuncAttributeMaxDynamicSharedMemorySize, SMEM_Q);
    gemm_q_h<<<dim3(64, 2), 256, SMEM_Q>>>();

    cudaFuncSetAttribute(attn_qk_kernel, cudaFuncAttributeMaxDynamicSharedMemorySize, SMEM_QK);
    attn_qk_kernel<<<dim3(B_, NMT), 256, SMEM_QK>>>(kin);

    rowinv_kernel<<<B_, 128>>>();

    cudaFuncSetAttribute(attn_av_kernel, cudaFuncAttributeMaxDynamicSharedMemorySize, SMEM_AV);
    attn_av_kernel<<<dim3(B_, 2, 4), 256, SMEM_AV>>>(vin);

    av_combine_kernel<<<(B_*NS*SD/4)/256, 256>>>();

    cudaFuncSetAttribute(gemm_ff0_h, cudaFuncAttributeMaxDynamicSharedMemorySize, SMEM_FF0);
    gemm_ff0_h<<<dim3(32, 8), 256, SMEM_FF0>>>();

    cudaFuncSetAttribute(gemm_out_h, cudaFuncAttributeMaxDynamicSharedMemorySize, SMEM_OUT);
    gemm_out_h<<<dim3(64, 2), 256, SMEM_OUT>>>((float*)d_out);
}